// round 15
// baseline (speedup 1.0000x reference)
#include <cuda_runtime.h>
#include <cuda_bf16.h>
#include <math.h>
#include <stdint.h>

#define BB 512
#define LL 25
#define EE 300
#define EEP 320
#define HH 1024
#define DD 256
#define TT 128
#define BL (BB*LL)
#define CATW (DD+HH)

// ---------------- scratch ----------------------------------------------------
__device__ __nv_bfloat16 g_x_hi[BL*EEP], g_x_lo[BL*EEP];
__device__ float g_gi_all[BL*3*HH];          // PERMUTED cols n=3j+gate
__device__ float g_enc_out[BL*HH];
__device__ float g_h[BB*HH];
__device__ __nv_bfloat16 g_h_hi[BB*HH],  g_h_lo[BB*HH];
__device__ __nv_bfloat16 g_h_hi2[BB*HH], g_h_lo2[BB*HH];
__device__ __nv_bfloat16 g_hb_hi[BB*HH], g_hb_lo[BB*HH];   // bn1(h) split
__device__ float g_gh[BB*3*HH];              // PERMUTED cols
__device__ int   g_tok[BB];
__device__ __nv_bfloat16 g_cat_hi[BB*CATW], g_cat_lo[BB*CATW];
__device__ __nv_bfloat16 g_o_hi[BB*HH], g_o_lo[BB*HH];
__device__ __nv_bfloat16 g_wencih_hi[3*HH*EEP], g_wencih_lo[3*HH*EEP];
__device__ __nv_bfloat16 g_wenchh_hi[3*HH*HH],  g_wenchh_lo[3*HH*HH];
__device__ __nv_bfloat16 g_wdecih_hi[3*HH*HH],  g_wdecih_lo[3*HH*HH];
__device__ __nv_bfloat16 g_wdechh_hi[3*HH*HH],  g_wdechh_lo[3*HH*HH];
__device__ __nv_bfloat16 g_wcomb_hi[HH*CATW],   g_wcomb_lo[HH*CATW];
__device__ __nv_bfloat16 g_wout_hi[TT*HH],      g_wout_lo[TT*HH];

__device__ unsigned g_bcnt[8];
__device__ volatile unsigned g_bgen[8];

__device__ __forceinline__ float sigmoidf_(float x) { return 1.f/(1.f+expf(-x)); }

__device__ __forceinline__ uint32_t smem_u32(const void* p) {
    uint32_t a;
    asm("{ .reg .u64 t; cvta.to.shared.u64 t, %1; cvt.u32.u64 %0, t; }" : "=r"(a) : "l"(p));
    return a;
}

__device__ __forceinline__ void gbar(int id, unsigned &gen, unsigned nb)
{
    __syncthreads();
    if (threadIdx.x == 0) {
        __threadfence();
        unsigned my = gen;
        if (atomicAdd(&g_bcnt[id], 1u) == nb - 1u) {
            g_bcnt[id] = 0;
            __threadfence();
            g_bgen[id] = my + 1u;
        } else {
            while (g_bgen[id] == my) { }
        }
        __threadfence();
    }
    __syncthreads();
    gen += 1u;
}

#define LDM4(r, addr) \
    asm volatile("ldmatrix.sync.aligned.m8n8.x4.shared.b16 {%0,%1,%2,%3}, [%4];" \
        : "=r"((r)[0]), "=r"((r)[1]), "=r"((r)[2]), "=r"((r)[3]) : "r"(addr))
#define LDM2(r, addr) \
    asm volatile("ldmatrix.sync.aligned.m8n8.x2.shared.b16 {%0,%1}, [%2];" \
        : "=r"((r)[0]), "=r"((r)[1]) : "r"(addr))
#define MMA16816(d, a, b) \
    asm volatile("mma.sync.aligned.m16n8k16.row.col.f32.bf16.bf16.f32 " \
        "{%0,%1,%2,%3}, {%4,%5,%6,%7}, {%8,%9}, {%0,%1,%2,%3};" \
        : "+f"((d)[0]), "+f"((d)[1]), "+f"((d)[2]), "+f"((d)[3]) \
        : "r"((a)[0]), "r"((a)[1]), "r"((a)[2]), "r"((a)[3]), "r"((b)[0]), "r"((b)[1]))
#define CPASYNC16(dst, src) \
    asm volatile("cp.async.cg.shared.global [%0], [%1], 16;" :: "r"(dst), "l"(src))

enum { EPI_C=0, EPI_COMB=1, EPI_GRU=2, EPI_LOGIT=3 };
#define GHS_LD 100
#define LSD 129

// T4: include the al*bl term (4-term split; used for logits only)
template<int EPI, int NT, int T4 = 0>
__device__ __forceinline__ void mma_body(
    char* sm, int bx, int by,
    const __nv_bfloat16* __restrict__ Ahi, const __nv_bfloat16* __restrict__ Alo, int lda,
    const __nv_bfloat16* __restrict__ Bhi, const __nv_bfloat16* __restrict__ Blo, int ldb,
    int K, float* __restrict__ Cf, int N,
    const float* __restrict__ bias, const float* __restrict__ bn,
    __nv_bfloat16* __restrict__ Ohi, __nv_bfloat16* __restrict__ Olo,
    const float* __restrict__ Gmat, int gstride, int l_is_gh,
    const float* __restrict__ bih, const float* __restrict__ bhh,
    float* __restrict__ hstate,
    __nv_bfloat16* __restrict__ hhi_out, __nv_bfloat16* __restrict__ hlo_out,
    float* __restrict__ eout, int eout_stride,
    const float* __restrict__ bnh,
    __nv_bfloat16* __restrict__ hbhi, __nv_bfloat16* __restrict__ hblo)
{
    constexpr int WNT = NT * 8;
    constexpr int NR  = 4 * WNT;
    constexpr int BLO = NR * 128;
    constexpr int STG = 32768 + 2 * NR * 128;

    const int tid  = threadIdx.x;
    const int lane = tid & 31, wid = tid >> 5;
    const int wm   = wid & 3;
    const int wn   = wid >> 2;
    const int m0   = by * 128, n0 = bx * NR;
    const uint32_t sbase = smem_u32(sm);

    const int sr = tid >> 2, sq = tid & 3;
    const __nv_bfloat16* pa_hi = Ahi + (size_t)(m0 + sr) * lda;
    const __nv_bfloat16* pa_lo = Alo + (size_t)(m0 + sr) * lda;
    const int rbq = (sr < NR) ? sr : (NR - 1);
    const __nv_bfloat16* pb_hi = Bhi + (size_t)(n0 + rbq) * ldb;
    const __nv_bfloat16* pb_lo = Blo + (size_t)(n0 + rbq) * ldb;
    const uint32_t swr = (uint32_t)(sr & 7);

    auto stage = [&](int buf, int k0) {
        uint32_t dbase = sbase + (uint32_t)buf * STG;
        uint32_t da = dbase + (uint32_t)sr * 128u;
        #pragma unroll
        for (int c = 0; c < 2; c++) {
            uint32_t g = (uint32_t)(sq * 2 + c);
            uint32_t off = ((g ^ swr) << 4);
            CPASYNC16(da + off,          pa_hi + k0 + g * 8);
            CPASYNC16(da + 16384u + off, pa_lo + k0 + g * 8);
        }
        if (sr < NR) {
            uint32_t db = dbase + 32768u + (uint32_t)sr * 128u;
            #pragma unroll
            for (int c = 0; c < 2; c++) {
                uint32_t g = (uint32_t)(sq * 2 + c);
                uint32_t off = ((g ^ swr) << 4);
                CPASYNC16(db + off,                 pb_hi + k0 + g * 8);
                CPASYNC16(db + (uint32_t)BLO + off, pb_lo + k0 + g * 8);
            }
        }
        asm volatile("cp.async.commit_group;" ::: "memory");
    };

    float acc[2][NT][4];
    #pragma unroll
    for (int i = 0; i < 2; i++)
        #pragma unroll
        for (int j = 0; j < NT; j++)
            #pragma unroll
            for (int q = 0; q < 4; q++) acc[i][j][q] = 0.f;

    const int nt = K / 64;
    stage(0, 0);
    for (int it = 0; it < nt; it++) {
        if (it + 1 < nt) {
            stage((it + 1) & 1, (it + 1) * 64);
            asm volatile("cp.async.wait_group 1;" ::: "memory");
        } else {
            asm volatile("cp.async.wait_group 0;" ::: "memory");
        }
        __syncthreads();

        uint32_t tb = sbase + (uint32_t)(it & 1) * STG;
        #pragma unroll
        for (int ks = 0; ks < 4; ks++) {
            const int g0 = ks * 2;
            uint32_t ah[2][4], al[2][4];
            {
                int row_off = ((lane >> 3) & 1) * 8 + (lane & 7);
                int g = g0 + (lane >> 4);
                #pragma unroll
                for (int mt = 0; mt < 2; mt++) {
                    int row = wm * 32 + mt * 16 + row_off;
                    uint32_t addr = tb + (uint32_t)row * 128u
                                  + (uint32_t)((g ^ (row & 7)) << 4);
                    LDM4(ah[mt], addr);
                    LDM4(al[mt], addr + 16384u);
                }
            }
            uint32_t bh[NT][2], bl[NT][2];
            {
                int grp = lane >> 3;
                #pragma unroll
                for (int p = 0; p < NT/2; p++) {
                    int tile = 2 * p + (grp >> 1);
                    int g = g0 + (grp & 1);
                    int nrow = wn * WNT + tile * 8 + (lane & 7);
                    uint32_t addr = tb + 32768u + (uint32_t)nrow * 128u
                                  + (uint32_t)((g ^ (nrow & 7)) << 4);
                    uint32_t r4[4];
                    LDM4(r4, addr);
                    bh[2*p][0] = r4[0]; bh[2*p][1] = r4[1];
                    bh[2*p+1][0] = r4[2]; bh[2*p+1][1] = r4[3];
                    LDM4(r4, addr + BLO);
                    bl[2*p][0] = r4[0]; bl[2*p][1] = r4[1];
                    bl[2*p+1][0] = r4[2]; bl[2*p+1][1] = r4[3];
                }
                if (NT & 1) {
                    int tile = NT - 1;
                    int g = g0 + (grp & 1);
                    int nrow = wn * WNT + tile * 8 + (lane & 7);
                    uint32_t addr = tb + 32768u + (uint32_t)nrow * 128u
                                  + (uint32_t)((g ^ (nrow & 7)) << 4);
                    LDM2(bh[NT-1], addr);
                    LDM2(bl[NT-1], addr + BLO);
                }
            }
            #pragma unroll
            for (int mt = 0; mt < 2; mt++)
                #pragma unroll
                for (int ntl = 0; ntl < NT; ntl++)
                    MMA16816(acc[mt][ntl], ah[mt], bh[ntl]);
            #pragma unroll
            for (int mt = 0; mt < 2; mt++)
                #pragma unroll
                for (int ntl = 0; ntl < NT; ntl++)
                    MMA16816(acc[mt][ntl], ah[mt], bl[ntl]);
            #pragma unroll
            for (int mt = 0; mt < 2; mt++)
                #pragma unroll
                for (int ntl = 0; ntl < NT; ntl++)
                    MMA16816(acc[mt][ntl], al[mt], bh[ntl]);
            if (T4) {
                #pragma unroll
                for (int mt = 0; mt < 2; mt++)
                    #pragma unroll
                    for (int ntl = 0; ntl < NT; ntl++)
                        MMA16816(acc[mt][ntl], al[mt], bl[ntl]);
            }
        }
        __syncthreads();
    }

    if (EPI == EPI_GRU) {
        float* ghs = (float*)sm;
        #pragma unroll
        for (int mt = 0; mt < 2; mt++) {
            #pragma unroll
            for (int ntl = 0; ntl < NT; ntl++) {
                int rl = wm*32 + mt*16 + (lane >> 2);
                int cl = wn*WNT + ntl*8 + (lane & 3)*2;
                ghs[rl*GHS_LD + cl]     = acc[mt][ntl][0];
                ghs[rl*GHS_LD + cl + 1] = acc[mt][ntl][1];
                ghs[(rl+8)*GHS_LD + cl]     = acc[mt][ntl][2];
                ghs[(rl+8)*GHS_LD + cl + 1] = acc[mt][ntl][3];
            }
        }
        __syncthreads();
        float s1=0.f, mu1=0.f, be1=0.f;
        if (hbhi) { s1 = bnh[0]*rsqrtf(bnh[3]+1e-5f); mu1 = bnh[2]; be1 = bnh[1]; }
        const int j0 = n0 / 3;
        for (int i = tid; i < 128*32; i += 512) {
            int bl = i >> 5, jl = i & 31;
            int b = m0 + bl;
            int j = j0 + jl;
            float L0 = ghs[bl*GHS_LD + 3*jl + 0];
            float L1 = ghs[bl*GHS_LD + 3*jl + 1];
            float L2 = ghs[bl*GHS_LD + 3*jl + 2];
            const float* G = Gmat + (size_t)b*gstride + (n0 + 3*jl);
            float G0 = G[0], G1 = G[1], G2 = G[2];
            float i_r, i_z, i_n, h_r, h_z, h_n;
            if (l_is_gh) { h_r=L0; h_z=L1; h_n=L2; i_r=G0; i_z=G1; i_n=G2; }
            else         { i_r=L0; i_z=L1; i_n=L2; h_r=G0; h_z=G1; h_n=G2; }
            i_r += bih[j]; i_z += bih[HH+j]; i_n += bih[2*HH+j];
            h_r += bhh[j]; h_z += bhh[HH+j]; h_n += bhh[2*HH+j];
            float r = sigmoidf_(i_r + h_r);
            float z = sigmoidf_(i_z + h_z);
            float n = tanhf(i_n + r*h_n);
            float hold = hstate[(size_t)b*HH + j];
            float hn2 = (1.f - z)*n + z*hold;
            hstate[(size_t)b*HH + j] = hn2;
            __nv_bfloat16 hb = __float2bfloat16(hn2);
            hhi_out[(size_t)b*HH + j] = hb;
            hlo_out[(size_t)b*HH + j] = __float2bfloat16(hn2 - __bfloat162float(hb));
            if (hbhi) {
                float hv = (hn2 - mu1)*s1 + be1;
                __nv_bfloat16 hbb = __float2bfloat16(hv);
                hbhi[(size_t)b*HH + j] = hbb;
                hblo[(size_t)b*HH + j] = __float2bfloat16(hv - __bfloat162float(hbb));
            }
            if (eout) eout[(size_t)b*eout_stride + j] = hn2;
        }
        return;
    }

    if (EPI == EPI_LOGIT) {
        // stage logits(+bias) to smem, then fused log_softmax + argmax.
        // Cf = out base; bias = out_b; gstride = lsm_t.
        float* ls = (float*)sm;
        #pragma unroll
        for (int mt = 0; mt < 2; mt++) {
            #pragma unroll
            for (int ntl = 0; ntl < NT; ntl++) {
                int rl = wm*32 + mt*16 + (lane >> 2);
                int cl = wn*WNT + ntl*8 + (lane & 3)*2;
                ls[rl*LSD + cl]     = acc[mt][ntl][0] + bias[cl];
                ls[rl*LSD + cl + 1] = acc[mt][ntl][1] + bias[cl+1];
                ls[(rl+8)*LSD + cl]     = acc[mt][ntl][2] + bias[cl];
                ls[(rl+8)*LSD + cl + 1] = acc[mt][ntl][3] + bias[cl+1];
            }
        }
        __syncthreads();
        const int r = tid >> 2, q = tid & 3;
        const int b = m0 + r;
        float m = -1e30f; int am = 0;
        #pragma unroll 8
        for (int c = q*32; c < q*32+32; c++) {
            float v = ls[r*LSD + c];
            if (v > m) { m = v; am = c; }
        }
        #pragma unroll
        for (int off = 1; off < 4; off <<= 1) {
            float mo = __shfl_xor_sync(0xffffffffu, m, off);
            int   ao = __shfl_xor_sync(0xffffffffu, am, off);
            if (mo > m || (mo == m && ao < am)) { m = mo; am = ao; }
        }
        float s = 0.f;
        #pragma unroll 8
        for (int c = q*32; c < q*32+32; c++) s += expf(ls[r*LSD + c] - m);
        #pragma unroll
        for (int off = 1; off < 4; off <<= 1) s += __shfl_xor_sync(0xffffffffu, s, off);
        float lse = logf(s);
        float* orow = Cf + ((size_t)b*LL + gstride)*TT;
        #pragma unroll 8
        for (int c = q*32; c < q*32+32; c++) orow[c] = ls[r*LSD + c] - m - lse;
        if (q == 0) g_tok[b] = am;
        return;
    }

    float s = 1.f, mu = 0.f, be = 0.f;
    if (EPI == EPI_COMB) { s = bn[0]*rsqrtf(bn[3]+1e-5f); mu = bn[2]; be = bn[1]; }
    #pragma unroll
    for (int mt = 0; mt < 2; mt++) {
        #pragma unroll
        for (int ntl = 0; ntl < NT; ntl++) {
            int row = m0 + wm*32 + mt*16 + (lane >> 2);
            int col = n0 + wn*WNT + ntl*8 + (lane & 3)*2;
            if (EPI == EPI_C) {
                *(float2*)(Cf + (size_t)row*N + col) =
                    make_float2(acc[mt][ntl][0], acc[mt][ntl][1]);
                *(float2*)(Cf + (size_t)(row+8)*N + col) =
                    make_float2(acc[mt][ntl][2], acc[mt][ntl][3]);
            } else {
                #pragma unroll
                for (int q = 0; q < 4; q++) {
                    int r = row + (q >> 1)*8;
                    int c = col + (q & 1);
                    float v = acc[mt][ntl][q] + bias[c];
                    v = fmaxf((v - mu)*s + be, 0.f);
                    __nv_bfloat16 hv = __float2bfloat16(v);
                    Ohi[(size_t)r*HH + c] = hv;
                    Olo[(size_t)r*HH + c] = __float2bfloat16(v - __bfloat162float(hv));
                }
            }
        }
    }
}

// ---------------- attention phase (two 256-thread groups) ---------------------
struct LAS {
    float sh[HH];
    float red[256];
    float semb[DD];
    float saw[32];
    float pad[8];
};
#define NBAR(g) asm volatile("bar.sync %0, 256;" :: "r"((g)+1) : "memory")

__device__ void attn_phase(char* smb, int blk,
    const float* __restrict__ dec_emb,
    const float* __restrict__ attn_W, const float* __restrict__ attn_b,
    int use_tok)
{
    const int tid = threadIdx.x;
    const int group = tid >> 8;
    const int gtid = tid & 255;
    LAS* S = ((LAS*)smb) + group;
    __syncthreads();

    for (int rep = 0; rep < 2; rep++) {
        int b = blk + (group*2 + rep)*128;
        for (int k = gtid; k < HH; k += 256) S->sh[k] = g_h[(size_t)b*HH + k];
        int token = use_tok ? g_tok[b] : TT;

        float val = dec_emb[(size_t)token*DD + gtid];
        S->red[gtid] = val*val; NBAR(group);
        for (int st=128; st>0; st>>=1) { if (gtid<st) S->red[gtid]+=S->red[gtid+st]; NBAR(group); }
        float sc = fminf(1.f, 1.f/(sqrtf(S->red[0])+1e-7f));
        float e = val*sc;
        S->semb[gtid] = e;
        {
            __nv_bfloat16 h = __float2bfloat16(e);
            g_cat_hi[(size_t)b*CATW + gtid] = h;
            g_cat_lo[(size_t)b*CATW + gtid] = __float2bfloat16(e - __bfloat162float(h));
        }
        NBAR(group);

        int warp = gtid>>5, lane = gtid&31;
        for (int l = warp; l < LL; l += 8) {
            const float* w = attn_W + (size_t)l*CATW;
            float acc = 0.f;
            for (int k = lane; k < DD; k += 32) acc += S->semb[k]*w[k];
            for (int k = lane; k < HH; k += 32) acc += S->sh[k]*w[DD+k];
            for (int o=16;o;o>>=1) acc += __shfl_xor_sync(0xffffffffu, acc, o);
            if (lane==0) S->saw[l] = acc + attn_b[l];
        }
        NBAR(group);
        if (warp==0) {
            float v = (lane<LL)? S->saw[lane] : -1e30f;
            float m = v;
            for (int o=16;o;o>>=1) m = fmaxf(m, __shfl_xor_sync(0xffffffffu, m, o));
            float ex = (lane<LL)? expf(v-m) : 0.f;
            float sm2 = ex;
            for (int o=16;o;o>>=1) sm2 += __shfl_xor_sync(0xffffffffu, sm2, o);
            if (lane<LL) S->saw[lane] = ex/sm2;
        }
        NBAR(group);

        const float* eo = g_enc_out + (size_t)b*LL*HH;
        for (int j = gtid; j < HH; j += 256) {
            float acc = 0.f;
            #pragma unroll
            for (int l=0;l<LL;l++) acc += S->saw[l]*eo[(size_t)l*HH + j];
            __nv_bfloat16 h = __float2bfloat16(acc);
            g_cat_hi[(size_t)b*CATW + DD + j] = h;
            g_cat_lo[(size_t)b*CATW + DD + j] = __float2bfloat16(acc - __bfloat162float(h));
        }
        NBAR(group);
    }
    __syncthreads();
}

// ---------------- persistent encoder -----------------------------------------
__global__ __launch_bounds__(512) void enc_persistent(
    const float* __restrict__ bih, const float* __restrict__ bhh)
{
    extern __shared__ char sm[];
    unsigned gen = 0;
    const int bx = blockIdx.x & 31, by = blockIdx.x >> 5;
    for (int t = 0; t < LL; t++) {
        int p = t & 1;
        const __nv_bfloat16* ah = p ? g_h_hi2 : g_h_hi;
        const __nv_bfloat16* al = p ? g_h_lo2 : g_h_lo;
        __nv_bfloat16* oh = p ? g_h_hi : g_h_hi2;
        __nv_bfloat16* ol = p ? g_h_lo : g_h_lo2;
        mma_body<EPI_GRU,3>(sm, bx, by, ah, al, HH,
                            g_wenchh_hi, g_wenchh_lo, HH, HH,
                            nullptr, 3*HH, nullptr, nullptr, nullptr, nullptr,
                            g_gi_all + (size_t)t*3*HH, LL*3*HH, 1,
                            bih, bhh, g_h, oh, ol,
                            g_enc_out + (size_t)t*HH, LL*HH,
                            nullptr, nullptr, nullptr);
        if (t < LL-1) gbar(by, gen, 32);
    }
}

// ---------------- persistent decoder -----------------------------------------
__global__ __launch_bounds__(512) void dec_persistent(
    const float* __restrict__ dec_emb,
    const float* __restrict__ attn_W, const float* __restrict__ attn_b,
    const float* __restrict__ out_b, const float* __restrict__ bn1,
    const float* __restrict__ comb_b, const float* __restrict__ bn2,
    const float* __restrict__ dec_bih, const float* __restrict__ dec_bhh,
    float* __restrict__ out)
{
    extern __shared__ char sm[];
    unsigned gen = 0;
    const int bi = blockIdx.x;

    // pre: SOS embedding + attention -> cat(0)
    attn_phase(sm, bi, dec_emb, attn_W, attn_b, 0);
    gbar(4, gen, gridDim.x);
    // pre: gh(0) = h_enc @ Whh (96 blocks)
    if (bi < 96) {
        mma_body<EPI_C,4>(sm, bi % 24, bi / 24,
            g_h_hi2, g_h_lo2, HH, g_wdechh_hi, g_wdechh_lo, HH, HH,
            g_gh, 3*HH, nullptr, nullptr, nullptr, nullptr,
            nullptr, 0, 0, nullptr, nullptr, nullptr, nullptr, nullptr, nullptr, 0,
            nullptr, nullptr, nullptr);
    }
    gbar(4, gen, gridDim.x);

    for (int t = 0; t < LL; t++) {
        // P1: comb (cat -> o), NT=1, 128 blocks
        mma_body<EPI_COMB,1>(sm, bi & 31, bi >> 5,
            g_cat_hi, g_cat_lo, CATW, g_wcomb_hi, g_wcomb_lo, CATW, CATW,
            nullptr, HH, comb_b, bn2, g_o_hi, g_o_lo,
            nullptr, 0, 0, nullptr, nullptr, nullptr, nullptr, nullptr, nullptr, 0,
            nullptr, nullptr, nullptr);
        gbar(4, gen, gridDim.x);
        // P2: gi + GRU (writes bn1(h) split for logits)
        mma_body<EPI_GRU,3>(sm, bi & 31, bi >> 5,
            g_o_hi, g_o_lo, HH, g_wdecih_hi, g_wdecih_lo, HH, HH,
            nullptr, 3*HH, nullptr, nullptr, nullptr, nullptr,
            g_gh, 3*HH, 0, dec_bih, dec_bhh, g_h, g_h_hi2, g_h_lo2,
            nullptr, 0,
            bn1, g_hb_hi, g_hb_lo);
        gbar(4, gen, gridDim.x);
        // P3: gh(t+1) on 0..95 (skip on last); logits+lsm+argmax (4-term) on 96..99
        if (bi < 96) {
            if (t < LL-1) {
                mma_body<EPI_C,4>(sm, bi % 24, bi / 24,
                    g_h_hi2, g_h_lo2, HH, g_wdechh_hi, g_wdechh_lo, HH, HH,
                    g_gh, 3*HH, nullptr, nullptr, nullptr, nullptr,
                    nullptr, 0, 0, nullptr, nullptr, nullptr, nullptr, nullptr, nullptr, 0,
                    nullptr, nullptr, nullptr);
            }
        } else if (bi < 100) {
            mma_body<EPI_LOGIT,4,1>(sm, 0, bi - 96,
                g_hb_hi, g_hb_lo, HH, g_wout_hi, g_wout_lo, HH, HH,
                out, TT, out_b, nullptr, nullptr, nullptr,
                nullptr, t, 0, nullptr, nullptr, nullptr, nullptr, nullptr, nullptr, 0,
                nullptr, nullptr, nullptr);
        }
        gbar(4, gen, gridDim.x);
        // P4: attention(t+1) -> cat (skipped entirely on last step)
        if (t < LL-1) {
            attn_phase(sm, bi, dec_emb, attn_W, attn_b, 1);
            gbar(4, gen, gridDim.x);
        }
    }
}

// ---------------- weight splits -----------------------------------------------
__device__ __forceinline__ void split_perm(const float* src, __nv_bfloat16* hi,
                                           __nv_bfloat16* lo, int idx, int K, int Kpad)
{
    int n_new = idx / Kpad, k = idx - n_new*Kpad;
    int j = n_new / 3, gate = n_new - 3*j;
    float v = (k < K) ? src[(size_t)(gate*HH + j)*K + k] : 0.f;
    __nv_bfloat16 h = __float2bfloat16(v);
    hi[idx] = h;
    lo[idx] = __float2bfloat16(v - __bfloat162float(h));
}
__device__ __forceinline__ void split_seg(const float* src, __nv_bfloat16* hi,
                                          __nv_bfloat16* lo, int idx, int K, int Kpad)
{
    int r = idx / Kpad, k = idx - r*Kpad;
    float v = (k < K) ? src[(size_t)r*K + k] : 0.f;
    __nv_bfloat16 h = __float2bfloat16(v);
    hi[idx] = h;
    lo[idx] = __float2bfloat16(v - __bfloat162float(h));
}

__global__ void split_a_kernel(const float* __restrict__ w_eih, const float* __restrict__ w_ehh)
{
    int idx = blockIdx.x*blockDim.x + threadIdx.x;
    const int n0 = 3*HH*EEP, n1 = 3*HH*HH;
    if (idx < n0) split_perm(w_eih, g_wencih_hi, g_wencih_lo, idx, EE, EEP);
    else if (idx < n0 + n1) split_perm(w_ehh, g_wenchh_hi, g_wenchh_lo, idx - n0, HH, HH);
}

__global__ void split_b_kernel(const float* __restrict__ w_dih, const float* __restrict__ w_dhh,
                               const float* __restrict__ w_cmb, const float* __restrict__ w_out)
{
    int idx = blockIdx.x*blockDim.x + threadIdx.x;
    const int n0 = 3*HH*HH, n1 = 3*HH*HH, n2 = HH*CATW, n3 = TT*HH;
    if (idx < n0) split_perm(w_dih, g_wdecih_hi, g_wdecih_lo, idx, HH, HH);
    else if (idx < n0+n1) split_perm(w_dhh, g_wdechh_hi, g_wdechh_lo, idx - n0, HH, HH);
    else if (idx < n0+n1+n2) split_seg(w_cmb, g_wcomb_hi, g_wcomb_lo, idx - n0 - n1, CATW, CATW);
    else if (idx < n0+n1+n2+n3) split_seg(w_out, g_wout_hi, g_wout_lo, idx - n0 - n1 - n2, HH, HH);
}

// ---------------- misc kernels ------------------------------------------------
__global__ void init_kernel()
{
    int idx = blockIdx.x*blockDim.x + threadIdx.x;
    if (idx < BB*HH) {
        g_h[idx] = 0.f;
        g_h_hi[idx] = __float2bfloat16(0.f);
        g_h_lo[idx] = __float2bfloat16(0.f);
    }
    if (idx < 8) { g_bcnt[idx] = 0; g_bgen[idx] = 0; }
}

__global__ void embed_renorm_kernel(const int* __restrict__ tokens,
                                    const float* __restrict__ w2v)
{
    int row = blockIdx.x;
    int tok = tokens[row];
    const float* src = w2v + (size_t)tok*EE;
    __shared__ float red[128];
    float ss = 0.f;
    for (int k = threadIdx.x; k < EE; k += blockDim.x) { float v = src[k]; ss += v*v; }
    red[threadIdx.x] = ss; __syncthreads();
    for (int s = blockDim.x>>1; s>0; s>>=1) {
        if (threadIdx.x < s) red[threadIdx.x] += red[threadIdx.x+s];
        __syncthreads();
    }
    float sc = fminf(1.f, 10.f/(sqrtf(red[0])+1e-7f));
    for (int k = threadIdx.x; k < EE; k += blockDim.x) {
        float v = src[k]*sc;
        __nv_bfloat16 h = __float2bfloat16(v);
        g_x_hi[(size_t)row*EEP + k] = h;
        g_x_lo[(size_t)row*EEP + k] = __float2bfloat16(v - __bfloat162float(h));
    }
    for (int k = EE + threadIdx.x; k < EEP; k += blockDim.x) {
        g_x_hi[(size_t)row*EEP + k] = __float2bfloat16(0.f);
        g_x_lo[(size_t)row*EEP + k] = __float2bfloat16(0.f);
    }
}

// plain GEMM for gi one-shot (NT=3)
__global__ __launch_bounds__(512) void mma_gemm(
    const __nv_bfloat16* __restrict__ Ahi, const __nv_bfloat16* __restrict__ Alo, int lda,
    const __nv_bfloat16* __restrict__ Bhi, const __nv_bfloat16* __restrict__ Blo, int ldb,
    int K, float* __restrict__ Cf, int N)
{
    extern __shared__ char sm[];
    mma_body<EPI_C,3>(sm, blockIdx.x, blockIdx.y, Ahi, Alo, lda, Bhi, Blo, ldb,
                      K, Cf, N, nullptr, nullptr, nullptr, nullptr,
                      nullptr, 0, 0, nullptr, nullptr, nullptr, nullptr, nullptr, nullptr, 0,
                      nullptr, nullptr, nullptr);
}

// ---------------- launch ------------------------------------------------------
extern "C" void kernel_launch(void* const* d_in, const int* in_sizes, int n_in,
                              void* d_out, int out_size)
{
    const int*   tokens  = (const int*)  d_in[0];
    const float* w2v     = (const float*)d_in[1];
    const float* enc_Wih = (const float*)d_in[2];
    const float* enc_Whh = (const float*)d_in[3];
    const float* enc_bih = (const float*)d_in[4];
    const float* enc_bhh = (const float*)d_in[5];
    const float* dec_emb = (const float*)d_in[6];
    const float* attn_W  = (const float*)d_in[7];
    const float* attn_b  = (const float*)d_in[8];
    const float* comb_W  = (const float*)d_in[9];
    const float* comb_b  = (const float*)d_in[10];
    const float* dec_Wih = (const float*)d_in[11];
    const float* dec_Whh = (const float*)d_in[12];
    const float* dec_bih = (const float*)d_in[13];
    const float* dec_bhh = (const float*)d_in[14];
    const float* out_W   = (const float*)d_in[15];
    const float* out_b   = (const float*)d_in[16];
    const float* bn1     = (const float*)d_in[17];
    const float* bn2     = (const float*)d_in[18];
    float* out = (float*)d_out;

    __nv_bfloat16 *pxh, *pxl, *pw_eih_h, *pw_eih_l;
    float *pgi_all;
    cudaGetSymbolAddress((void**)&pxh, g_x_hi);
    cudaGetSymbolAddress((void**)&pxl, g_x_lo);
    cudaGetSymbolAddress((void**)&pw_eih_h, g_wencih_hi);
    cudaGetSymbolAddress((void**)&pw_eih_l, g_wencih_lo);
    cudaGetSymbolAddress((void**)&pgi_all,  g_gi_all);

    const int STG3 = 32768 + 2*96*128;     // 57344
    const int STG4 = 32768 + 2*128*128;    // 65536
    const int SMEM_G   = 2 * STG3;         // 114688
    const int SMEM_DEC = 2 * STG4;         // 131072 (>= 128*129*4 for logit lsm)
    cudaFuncSetAttribute(mma_gemm,       cudaFuncAttributeMaxDynamicSharedMemorySize, SMEM_G);
    cudaFuncSetAttribute(enc_persistent, cudaFuncAttributeMaxDynamicSharedMemorySize, SMEM_G);
    cudaFuncSetAttribute(dec_persistent, cudaFuncAttributeMaxDynamicSharedMemorySize, SMEM_DEC);

    init_kernel<<<2048, 256>>>();                                          // 0
    split_a_kernel<<<(3*HH*EEP + 3*HH*HH + 255)/256, 256>>>(enc_Wih, enc_Whh);    // 1
    split_b_kernel<<<(2*3*HH*HH + HH*CATW + TT*HH + 255)/256, 256>>>(      // 2
        dec_Wih, dec_Whh, comb_W, out_W);
    embed_renorm_kernel<<<BL, 128>>>(tokens, w2v);                         // 3
    mma_gemm<<<dim3(3*HH/96, BL/128), 512, SMEM_G>>>(                      // 4
        pxh, pxl, EEP, pw_eih_h, pw_eih_l, EEP, EEP, pgi_all, 3*HH);
    enc_persistent<<<128, 512, SMEM_G>>>(enc_bih, enc_bhh);                // 5
    dec_persistent<<<128, 512, SMEM_DEC>>>(dec_emb, attn_W, attn_b,        // 6
        out_b, bn1, comb_b, bn2, dec_bih, dec_bhh, out);
}

// round 16
// speedup vs baseline: 1.0996x; 1.0996x over previous
#include <cuda_runtime.h>
#include <cuda_bf16.h>
#include <math.h>
#include <stdint.h>

#define BB 512
#define LL 25
#define EE 300
#define EEP 320
#define HH 1024
#define DD 256
#define TT 128
#define BL (BB*LL)
#define CATW (DD+HH)

// ---------------- scratch ----------------------------------------------------
__device__ __nv_bfloat16 g_x_hi[BL*EEP], g_x_lo[BL*EEP];
__device__ float g_gi_all[BL*3*HH];          // PERMUTED cols n=3j+gate
__device__ float g_enc_out[BL*HH];
__device__ float g_h[BB*HH];
__device__ __nv_bfloat16 g_h_hi[BB*HH],  g_h_lo[BB*HH];
__device__ __nv_bfloat16 g_h_hi2[BB*HH], g_h_lo2[BB*HH];
__device__ __nv_bfloat16 g_hb_hi[BB*HH], g_hb_lo[BB*HH];   // bn1(h) split
__device__ float g_gh[BB*3*HH];              // PERMUTED cols
__device__ float g_logits[2*BB*TT];          // split-K partials
__device__ __nv_bfloat16 g_cat_hi[BB*CATW], g_cat_lo[BB*CATW];
__device__ __nv_bfloat16 g_o_hi[BB*HH], g_o_lo[BB*HH];
__device__ __nv_bfloat16 g_wencih_hi[3*HH*EEP], g_wencih_lo[3*HH*EEP];
__device__ __nv_bfloat16 g_wenchh_hi[3*HH*HH],  g_wenchh_lo[3*HH*HH];
__device__ __nv_bfloat16 g_wdecih_hi[3*HH*HH],  g_wdecih_lo[3*HH*HH];
__device__ __nv_bfloat16 g_wdechh_hi[3*HH*HH],  g_wdechh_lo[3*HH*HH];
__device__ __nv_bfloat16 g_wcomb_hi[HH*CATW],   g_wcomb_lo[HH*CATW];
__device__ __nv_bfloat16 g_wout_hi[TT*HH],      g_wout_lo[TT*HH];

__device__ unsigned g_bcnt[8];
__device__ volatile unsigned g_bgen[8];

__device__ __forceinline__ float sigmoidf_(float x) { return 1.f/(1.f+expf(-x)); }

__device__ __forceinline__ uint32_t smem_u32(const void* p) {
    uint32_t a;
    asm("{ .reg .u64 t; cvta.to.shared.u64 t, %1; cvt.u32.u64 %0, t; }" : "=r"(a) : "l"(p));
    return a;
}

__device__ __forceinline__ void gbar(int id, unsigned &gen, unsigned nb)
{
    __syncthreads();
    if (threadIdx.x == 0) {
        __threadfence();
        unsigned my = gen;
        if (atomicAdd(&g_bcnt[id], 1u) == nb - 1u) {
            g_bcnt[id] = 0;
            __threadfence();
            g_bgen[id] = my + 1u;
        } else {
            while (g_bgen[id] == my) { }
        }
        __threadfence();
    }
    __syncthreads();
    gen += 1u;
}

#define LDM4(r, addr) \
    asm volatile("ldmatrix.sync.aligned.m8n8.x4.shared.b16 {%0,%1,%2,%3}, [%4];" \
        : "=r"((r)[0]), "=r"((r)[1]), "=r"((r)[2]), "=r"((r)[3]) : "r"(addr))
#define LDM2(r, addr) \
    asm volatile("ldmatrix.sync.aligned.m8n8.x2.shared.b16 {%0,%1}, [%2];" \
        : "=r"((r)[0]), "=r"((r)[1]) : "r"(addr))
#define MMA16816(d, a, b) \
    asm volatile("mma.sync.aligned.m16n8k16.row.col.f32.bf16.bf16.f32 " \
        "{%0,%1,%2,%3}, {%4,%5,%6,%7}, {%8,%9}, {%0,%1,%2,%3};" \
        : "+f"((d)[0]), "+f"((d)[1]), "+f"((d)[2]), "+f"((d)[3]) \
        : "r"((a)[0]), "r"((a)[1]), "r"((a)[2]), "r"((a)[3]), "r"((b)[0]), "r"((b)[1]))
#define CPASYNC16(dst, src) \
    asm volatile("cp.async.cg.shared.global [%0], [%1], 16;" :: "r"(dst), "l"(src))

enum { EPI_C=0, EPI_COMB=1, EPI_GRU=2 };
#define GHS_LD 100

// T4: include the al*bl term (4-term split; logits only)
template<int EPI, int NT, int T4 = 0>
__device__ __forceinline__ void mma_body(
    char* sm, int bx, int by,
    const __nv_bfloat16* __restrict__ Ahi, const __nv_bfloat16* __restrict__ Alo, int lda,
    const __nv_bfloat16* __restrict__ Bhi, const __nv_bfloat16* __restrict__ Blo, int ldb,
    int K, float* __restrict__ Cf, int N,
    const float* __restrict__ bias, const float* __restrict__ bn,
    __nv_bfloat16* __restrict__ Ohi, __nv_bfloat16* __restrict__ Olo,
    const float* __restrict__ Gmat, int gstride, int l_is_gh,
    const float* __restrict__ bih, const float* __restrict__ bhh,
    float* __restrict__ hstate,
    __nv_bfloat16* __restrict__ hhi_out, __nv_bfloat16* __restrict__ hlo_out,
    float* __restrict__ eout, int eout_stride,
    const float* __restrict__ bnh,
    __nv_bfloat16* __restrict__ hbhi, __nv_bfloat16* __restrict__ hblo)
{
    constexpr int WNT = NT * 8;
    constexpr int NR  = 4 * WNT;
    constexpr int BLO = NR * 128;
    constexpr int STG = 32768 + 2 * NR * 128;

    const int tid  = threadIdx.x;
    const int lane = tid & 31, wid = tid >> 5;
    const int wm   = wid & 3;
    const int wn   = wid >> 2;
    const int m0   = by * 128, n0 = bx * NR;
    const uint32_t sbase = smem_u32(sm);

    const int sr = tid >> 2, sq = tid & 3;
    const __nv_bfloat16* pa_hi = Ahi + (size_t)(m0 + sr) * lda;
    const __nv_bfloat16* pa_lo = Alo + (size_t)(m0 + sr) * lda;
    const int rbq = (sr < NR) ? sr : (NR - 1);
    const __nv_bfloat16* pb_hi = Bhi + (size_t)(n0 + rbq) * ldb;
    const __nv_bfloat16* pb_lo = Blo + (size_t)(n0 + rbq) * ldb;
    const uint32_t swr = (uint32_t)(sr & 7);

    auto stage = [&](int buf, int k0) {
        uint32_t dbase = sbase + (uint32_t)buf * STG;
        uint32_t da = dbase + (uint32_t)sr * 128u;
        #pragma unroll
        for (int c = 0; c < 2; c++) {
            uint32_t g = (uint32_t)(sq * 2 + c);
            uint32_t off = ((g ^ swr) << 4);
            CPASYNC16(da + off,          pa_hi + k0 + g * 8);
            CPASYNC16(da + 16384u + off, pa_lo + k0 + g * 8);
        }
        if (sr < NR) {
            uint32_t db = dbase + 32768u + (uint32_t)sr * 128u;
            #pragma unroll
            for (int c = 0; c < 2; c++) {
                uint32_t g = (uint32_t)(sq * 2 + c);
                uint32_t off = ((g ^ swr) << 4);
                CPASYNC16(db + off,                 pb_hi + k0 + g * 8);
                CPASYNC16(db + (uint32_t)BLO + off, pb_lo + k0 + g * 8);
            }
        }
        asm volatile("cp.async.commit_group;" ::: "memory");
    };

    float acc[2][NT][4];
    #pragma unroll
    for (int i = 0; i < 2; i++)
        #pragma unroll
        for (int j = 0; j < NT; j++)
            #pragma unroll
            for (int q = 0; q < 4; q++) acc[i][j][q] = 0.f;

    const int nt = K / 64;
    stage(0, 0);
    for (int it = 0; it < nt; it++) {
        if (it + 1 < nt) {
            stage((it + 1) & 1, (it + 1) * 64);
            asm volatile("cp.async.wait_group 1;" ::: "memory");
        } else {
            asm volatile("cp.async.wait_group 0;" ::: "memory");
        }
        __syncthreads();

        uint32_t tb = sbase + (uint32_t)(it & 1) * STG;
        #pragma unroll
        for (int ks = 0; ks < 4; ks++) {
            const int g0 = ks * 2;
            uint32_t ah[2][4], al[2][4];
            {
                int row_off = ((lane >> 3) & 1) * 8 + (lane & 7);
                int g = g0 + (lane >> 4);
                #pragma unroll
                for (int mt = 0; mt < 2; mt++) {
                    int row = wm * 32 + mt * 16 + row_off;
                    uint32_t addr = tb + (uint32_t)row * 128u
                                  + (uint32_t)((g ^ (row & 7)) << 4);
                    LDM4(ah[mt], addr);
                    LDM4(al[mt], addr + 16384u);
                }
            }
            uint32_t bh[NT][2], bl[NT][2];
            {
                int grp = lane >> 3;
                #pragma unroll
                for (int p = 0; p < NT/2; p++) {
                    int tile = 2 * p + (grp >> 1);
                    int g = g0 + (grp & 1);
                    int nrow = wn * WNT + tile * 8 + (lane & 7);
                    uint32_t addr = tb + 32768u + (uint32_t)nrow * 128u
                                  + (uint32_t)((g ^ (nrow & 7)) << 4);
                    uint32_t r4[4];
                    LDM4(r4, addr);
                    bh[2*p][0] = r4[0]; bh[2*p][1] = r4[1];
                    bh[2*p+1][0] = r4[2]; bh[2*p+1][1] = r4[3];
                    LDM4(r4, addr + BLO);
                    bl[2*p][0] = r4[0]; bl[2*p][1] = r4[1];
                    bl[2*p+1][0] = r4[2]; bl[2*p+1][1] = r4[3];
                }
                if (NT & 1) {
                    int tile = NT - 1;
                    int g = g0 + (grp & 1);
                    int nrow = wn * WNT + tile * 8 + (lane & 7);
                    uint32_t addr = tb + 32768u + (uint32_t)nrow * 128u
                                  + (uint32_t)((g ^ (nrow & 7)) << 4);
                    LDM2(bh[NT-1], addr);
                    LDM2(bl[NT-1], addr + BLO);
                }
            }
            #pragma unroll
            for (int mt = 0; mt < 2; mt++)
                #pragma unroll
                for (int ntl = 0; ntl < NT; ntl++)
                    MMA16816(acc[mt][ntl], ah[mt], bh[ntl]);
            #pragma unroll
            for (int mt = 0; mt < 2; mt++)
                #pragma unroll
                for (int ntl = 0; ntl < NT; ntl++)
                    MMA16816(acc[mt][ntl], ah[mt], bl[ntl]);
            #pragma unroll
            for (int mt = 0; mt < 2; mt++)
                #pragma unroll
                for (int ntl = 0; ntl < NT; ntl++)
                    MMA16816(acc[mt][ntl], al[mt], bh[ntl]);
            if (T4) {
                #pragma unroll
                for (int mt = 0; mt < 2; mt++)
                    #pragma unroll
                    for (int ntl = 0; ntl < NT; ntl++)
                        MMA16816(acc[mt][ntl], al[mt], bl[ntl]);
            }
        }
        __syncthreads();
    }

    if (EPI == EPI_GRU) {
        float* ghs = (float*)sm;
        #pragma unroll
        for (int mt = 0; mt < 2; mt++) {
            #pragma unroll
            for (int ntl = 0; ntl < NT; ntl++) {
                int rl = wm*32 + mt*16 + (lane >> 2);
                int cl = wn*WNT + ntl*8 + (lane & 3)*2;
                ghs[rl*GHS_LD + cl]     = acc[mt][ntl][0];
                ghs[rl*GHS_LD + cl + 1] = acc[mt][ntl][1];
                ghs[(rl+8)*GHS_LD + cl]     = acc[mt][ntl][2];
                ghs[(rl+8)*GHS_LD + cl + 1] = acc[mt][ntl][3];
            }
        }
        __syncthreads();
        float s1=0.f, mu1=0.f, be1=0.f;
        if (hbhi) { s1 = bnh[0]*rsqrtf(bnh[3]+1e-5f); mu1 = bnh[2]; be1 = bnh[1]; }
        const int j0 = n0 / 3;
        for (int i = tid; i < 128*32; i += 512) {
            int bl = i >> 5, jl = i & 31;
            int b = m0 + bl;
            int j = j0 + jl;
            float L0 = ghs[bl*GHS_LD + 3*jl + 0];
            float L1 = ghs[bl*GHS_LD + 3*jl + 1];
            float L2 = ghs[bl*GHS_LD + 3*jl + 2];
            const float* G = Gmat + (size_t)b*gstride + (n0 + 3*jl);
            float G0 = G[0], G1 = G[1], G2 = G[2];
            float i_r, i_z, i_n, h_r, h_z, h_n;
            if (l_is_gh) { h_r=L0; h_z=L1; h_n=L2; i_r=G0; i_z=G1; i_n=G2; }
            else         { i_r=L0; i_z=L1; i_n=L2; h_r=G0; h_z=G1; h_n=G2; }
            i_r += bih[j]; i_z += bih[HH+j]; i_n += bih[2*HH+j];
            h_r += bhh[j]; h_z += bhh[HH+j]; h_n += bhh[2*HH+j];
            float r = sigmoidf_(i_r + h_r);
            float z = sigmoidf_(i_z + h_z);
            float n = tanhf(i_n + r*h_n);
            float hold = hstate[(size_t)b*HH + j];
            float hn2 = (1.f - z)*n + z*hold;
            hstate[(size_t)b*HH + j] = hn2;
            __nv_bfloat16 hb = __float2bfloat16(hn2);
            hhi_out[(size_t)b*HH + j] = hb;
            hlo_out[(size_t)b*HH + j] = __float2bfloat16(hn2 - __bfloat162float(hb));
            if (hbhi) {
                float hv = (hn2 - mu1)*s1 + be1;
                __nv_bfloat16 hbb = __float2bfloat16(hv);
                hbhi[(size_t)b*HH + j] = hbb;
                hblo[(size_t)b*HH + j] = __float2bfloat16(hv - __bfloat162float(hbb));
            }
            if (eout) eout[(size_t)b*eout_stride + j] = hn2;
        }
        return;
    }

    float s = 1.f, mu = 0.f, be = 0.f;
    if (EPI == EPI_COMB) { s = bn[0]*rsqrtf(bn[3]+1e-5f); mu = bn[2]; be = bn[1]; }
    #pragma unroll
    for (int mt = 0; mt < 2; mt++) {
        #pragma unroll
        for (int ntl = 0; ntl < NT; ntl++) {
            int row = m0 + wm*32 + mt*16 + (lane >> 2);
            int col = n0 + wn*WNT + ntl*8 + (lane & 3)*2;
            if (EPI == EPI_C) {
                *(float2*)(Cf + (size_t)row*N + col) =
                    make_float2(acc[mt][ntl][0], acc[mt][ntl][1]);
                *(float2*)(Cf + (size_t)(row+8)*N + col) =
                    make_float2(acc[mt][ntl][2], acc[mt][ntl][3]);
            } else {
                #pragma unroll
                for (int q = 0; q < 4; q++) {
                    int r = row + (q >> 1)*8;
                    int c = col + (q & 1);
                    float v = acc[mt][ntl][q] + bias[c];
                    v = fmaxf((v - mu)*s + be, 0.f);
                    __nv_bfloat16 hv = __float2bfloat16(v);
                    Ohi[(size_t)r*HH + c] = hv;
                    Olo[(size_t)r*HH + c] = __float2bfloat16(v - __bfloat162float(hv));
                }
            }
        }
    }
}

// ---------------- lsm+attn phase (two 256-thread named-barrier groups) -------
struct LAS {
    float sh[HH];
    float red[256];
    int   redi[128];
    float semb[DD];
    float saw[32];
    float pad[8];
};
#define NBAR(g) asm volatile("bar.sync %0, 256;" :: "r"((g)+1) : "memory")

__device__ void lsm_attn_phase(char* smb, int blk,
    const float* __restrict__ dec_emb,
    const float* __restrict__ attn_W, const float* __restrict__ attn_b,
    const float* __restrict__ ob, float* __restrict__ out,
    int lsm_t, int do_attn)
{
    const int tid = threadIdx.x;
    const int group = tid >> 8;
    const int gtid = tid & 255;
    LAS* S = ((LAS*)smb) + group;
    __syncthreads();

    for (int rep = 0; rep < 2; rep++) {
        int b = blk + (group*2 + rep)*128;
        for (int k = gtid; k < HH; k += 256) S->sh[k] = g_h[(size_t)b*HH + k];
        NBAR(group);

        int token;
        if (lsm_t >= 0) {
            float x = 0.f;
            if (gtid < 128)
                x = g_logits[(size_t)b*TT + gtid]
                  + g_logits[(size_t)BB*TT + (size_t)b*TT + gtid] + ob[gtid];
            if (gtid < 128) { S->red[gtid] = x; S->redi[gtid] = gtid; }
            NBAR(group);
            for (int st = 64; st > 0; st >>= 1) {
                if (gtid < st && S->red[gtid+st] > S->red[gtid]) {
                    S->red[gtid] = S->red[gtid+st]; S->redi[gtid] = S->redi[gtid+st];
                }
                NBAR(group);
            }
            float m = S->red[0]; int am = S->redi[0];
            NBAR(group);
            S->red[gtid] = (gtid < 128) ? expf(x - m) : 0.f;
            NBAR(group);
            for (int st = 128; st > 0; st >>= 1) {
                if (gtid < st) S->red[gtid] += S->red[gtid+st];
                NBAR(group);
            }
            float lse = logf(S->red[0]);
            if (gtid < 128) out[((size_t)b*LL + lsm_t)*TT + gtid] = x - m - lse;
            token = am;
            NBAR(group);
        } else {
            token = TT;  // SOS
        }

        if (do_attn) {
            float val = dec_emb[(size_t)token*DD + gtid];
            S->red[gtid] = val*val; NBAR(group);
            for (int st=128; st>0; st>>=1) { if (gtid<st) S->red[gtid]+=S->red[gtid+st]; NBAR(group); }
            float sc = fminf(1.f, 1.f/(sqrtf(S->red[0])+1e-7f));
            float e = val*sc;
            S->semb[gtid] = e;
            {
                __nv_bfloat16 h = __float2bfloat16(e);
                g_cat_hi[(size_t)b*CATW + gtid] = h;
                g_cat_lo[(size_t)b*CATW + gtid] = __float2bfloat16(e - __bfloat162float(h));
            }
            NBAR(group);

            int warp = gtid>>5, lane = gtid&31;
            for (int l = warp; l < LL; l += 8) {
                const float* w = attn_W + (size_t)l*CATW;
                float acc = 0.f;
                for (int k = lane; k < DD; k += 32) acc += S->semb[k]*w[k];
                for (int k = lane; k < HH; k += 32) acc += S->sh[k]*w[DD+k];
                for (int o=16;o;o>>=1) acc += __shfl_xor_sync(0xffffffffu, acc, o);
                if (lane==0) S->saw[l] = acc + attn_b[l];
            }
            NBAR(group);
            if (warp==0) {
                float v = (lane<LL)? S->saw[lane] : -1e30f;
                float m = v;
                for (int o=16;o;o>>=1) m = fmaxf(m, __shfl_xor_sync(0xffffffffu, m, o));
                float ex = (lane<LL)? expf(v-m) : 0.f;
                float sm2 = ex;
                for (int o=16;o;o>>=1) sm2 += __shfl_xor_sync(0xffffffffu, sm2, o);
                if (lane<LL) S->saw[lane] = ex/sm2;
            }
            NBAR(group);

            const float* eo = g_enc_out + (size_t)b*LL*HH;
            for (int j = gtid; j < HH; j += 256) {
                float acc = 0.f;
                #pragma unroll
                for (int l=0;l<LL;l++) acc += S->saw[l]*eo[(size_t)l*HH + j];
                __nv_bfloat16 h = __float2bfloat16(acc);
                g_cat_hi[(size_t)b*CATW + DD + j] = h;
                g_cat_lo[(size_t)b*CATW + DD + j] = __float2bfloat16(acc - __bfloat162float(h));
            }
            NBAR(group);
        }
    }
    __syncthreads();
}

// ---------------- persistent encoder -----------------------------------------
__global__ __launch_bounds__(512) void enc_persistent(
    const float* __restrict__ bih, const float* __restrict__ bhh)
{
    extern __shared__ char sm[];
    unsigned gen = 0;
    const int bx = blockIdx.x & 31, by = blockIdx.x >> 5;
    for (int t = 0; t < LL; t++) {
        int p = t & 1;
        const __nv_bfloat16* ah = p ? g_h_hi2 : g_h_hi;
        const __nv_bfloat16* al = p ? g_h_lo2 : g_h_lo;
        __nv_bfloat16* oh = p ? g_h_hi : g_h_hi2;
        __nv_bfloat16* ol = p ? g_h_lo : g_h_lo2;
        mma_body<EPI_GRU,3>(sm, bx, by, ah, al, HH,
                            g_wenchh_hi, g_wenchh_lo, HH, HH,
                            nullptr, 3*HH, nullptr, nullptr, nullptr, nullptr,
                            g_gi_all + (size_t)t*3*HH, LL*3*HH, 1,
                            bih, bhh, g_h, oh, ol,
                            g_enc_out + (size_t)t*HH, LL*HH,
                            nullptr, nullptr, nullptr);
        if (t < LL-1) gbar(by, gen, 32);
    }
}

// ---------------- persistent decoder -----------------------------------------
__global__ __launch_bounds__(512) void dec_persistent(
    const float* __restrict__ dec_emb,
    const float* __restrict__ attn_W, const float* __restrict__ attn_b,
    const float* __restrict__ out_b, const float* __restrict__ bn1,
    const float* __restrict__ comb_b, const float* __restrict__ bn2,
    const float* __restrict__ dec_bih, const float* __restrict__ dec_bhh,
    float* __restrict__ out)
{
    extern __shared__ char sm[];
    unsigned gen = 0;
    const int bi = blockIdx.x;

    // pre: SOS embedding + attention -> cat(0)
    lsm_attn_phase(sm, bi, dec_emb, attn_W, attn_b, out_b, out, -1, 1);
    gbar(4, gen, gridDim.x);
    // pre: gh(0) = h_enc @ Whh (96 blocks)
    if (bi < 96) {
        mma_body<EPI_C,4>(sm, bi % 24, bi / 24,
            g_h_hi2, g_h_lo2, HH, g_wdechh_hi, g_wdechh_lo, HH, HH,
            g_gh, 3*HH, nullptr, nullptr, nullptr, nullptr,
            nullptr, 0, 0, nullptr, nullptr, nullptr, nullptr, nullptr, nullptr, 0,
            nullptr, nullptr, nullptr);
    }
    gbar(4, gen, gridDim.x);

    for (int t = 0; t < LL; t++) {
        // P1: comb (cat -> o), NT=1, 128 blocks
        mma_body<EPI_COMB,1>(sm, bi & 31, bi >> 5,
            g_cat_hi, g_cat_lo, CATW, g_wcomb_hi, g_wcomb_lo, CATW, CATW,
            nullptr, HH, comb_b, bn2, g_o_hi, g_o_lo,
            nullptr, 0, 0, nullptr, nullptr, nullptr, nullptr, nullptr, nullptr, 0,
            nullptr, nullptr, nullptr);
        gbar(4, gen, gridDim.x);
        // P2: gi + GRU (writes bn1(h) split for logits)
        mma_body<EPI_GRU,3>(sm, bi & 31, bi >> 5,
            g_o_hi, g_o_lo, HH, g_wdecih_hi, g_wdecih_lo, HH, HH,
            nullptr, 3*HH, nullptr, nullptr, nullptr, nullptr,
            g_gh, 3*HH, 0, dec_bih, dec_bhh, g_h, g_h_hi2, g_h_lo2,
            nullptr, 0,
            bn1, g_hb_hi, g_hb_lo);
        gbar(4, gen, gridDim.x);
        // P3: gh(t+1) on 0..95 (skip last); logits 4-term split-K on 96..103
        if (bi < 96) {
            if (t < LL-1) {
                mma_body<EPI_C,4>(sm, bi % 24, bi / 24,
                    g_h_hi2, g_h_lo2, HH, g_wdechh_hi, g_wdechh_lo, HH, HH,
                    g_gh, 3*HH, nullptr, nullptr, nullptr, nullptr,
                    nullptr, 0, 0, nullptr, nullptr, nullptr, nullptr, nullptr, nullptr, 0,
                    nullptr, nullptr, nullptr);
            }
        } else if (bi < 104) {
            int li = bi - 96;
            int half = li >> 2;           // K half: 0 or 1
            int byy  = li & 3;            // 4 row tiles of 128
            mma_body<EPI_C,4,1>(sm, 0, byy,
                g_hb_hi + half*512, g_hb_lo + half*512, HH,
                g_wout_hi + half*512, g_wout_lo + half*512, HH, 512,
                g_logits + (size_t)half*BB*TT, TT, nullptr, nullptr, nullptr, nullptr,
                nullptr, 0, 0, nullptr, nullptr, nullptr, nullptr, nullptr, nullptr, 0,
                nullptr, nullptr, nullptr);
        }
        gbar(4, gen, gridDim.x);
        // P4: lsm(t) + argmax + attn(t+1) -> cat
        lsm_attn_phase(sm, bi, dec_emb, attn_W, attn_b, out_b, out,
                       t, (t < LL-1));
        if (t < LL-1) gbar(4, gen, gridDim.x);
    }
}

// ---------------- weight splits -----------------------------------------------
__device__ __forceinline__ void split_perm(const float* src, __nv_bfloat16* hi,
                                           __nv_bfloat16* lo, int idx, int K, int Kpad)
{
    int n_new = idx / Kpad, k = idx - n_new*Kpad;
    int j = n_new / 3, gate = n_new - 3*j;
    float v = (k < K) ? src[(size_t)(gate*HH + j)*K + k] : 0.f;
    __nv_bfloat16 h = __float2bfloat16(v);
    hi[idx] = h;
    lo[idx] = __float2bfloat16(v - __bfloat162float(h));
}
__device__ __forceinline__ void split_seg(const float* src, __nv_bfloat16* hi,
                                          __nv_bfloat16* lo, int idx, int K, int Kpad)
{
    int r = idx / Kpad, k = idx - r*Kpad;
    float v = (k < K) ? src[(size_t)r*K + k] : 0.f;
    __nv_bfloat16 h = __float2bfloat16(v);
    hi[idx] = h;
    lo[idx] = __float2bfloat16(v - __bfloat162float(h));
}

__global__ void split_a_kernel(const float* __restrict__ w_eih, const float* __restrict__ w_ehh)
{
    int idx = blockIdx.x*blockDim.x + threadIdx.x;
    const int n0 = 3*HH*EEP, n1 = 3*HH*HH;
    if (idx < n0) split_perm(w_eih, g_wencih_hi, g_wencih_lo, idx, EE, EEP);
    else if (idx < n0 + n1) split_perm(w_ehh, g_wenchh_hi, g_wenchh_lo, idx - n0, HH, HH);
}

__global__ void split_b_kernel(const float* __restrict__ w_dih, const float* __restrict__ w_dhh,
                               const float* __restrict__ w_cmb, const float* __restrict__ w_out)
{
    int idx = blockIdx.x*blockDim.x + threadIdx.x;
    const int n0 = 3*HH*HH, n1 = 3*HH*HH, n2 = HH*CATW, n3 = TT*HH;
    if (idx < n0) split_perm(w_dih, g_wdecih_hi, g_wdecih_lo, idx, HH, HH);
    else if (idx < n0+n1) split_perm(w_dhh, g_wdechh_hi, g_wdechh_lo, idx - n0, HH, HH);
    else if (idx < n0+n1+n2) split_seg(w_cmb, g_wcomb_hi, g_wcomb_lo, idx - n0 - n1, CATW, CATW);
    else if (idx < n0+n1+n2+n3) split_seg(w_out, g_wout_hi, g_wout_lo, idx - n0 - n1 - n2, HH, HH);
}

// ---------------- misc kernels ------------------------------------------------
__global__ void init_kernel()
{
    int idx = blockIdx.x*blockDim.x + threadIdx.x;
    if (idx < BB*HH) {
        g_h[idx] = 0.f;
        g_h_hi[idx] = __float2bfloat16(0.f);
        g_h_lo[idx] = __float2bfloat16(0.f);
    }
    if (idx < 8) { g_bcnt[idx] = 0; g_bgen[idx] = 0; }
}

__global__ void embed_renorm_kernel(const int* __restrict__ tokens,
                                    const float* __restrict__ w2v)
{
    int row = blockIdx.x;
    int tok = tokens[row];
    const float* src = w2v + (size_t)tok*EE;
    __shared__ float red[128];
    float ss = 0.f;
    for (int k = threadIdx.x; k < EE; k += blockDim.x) { float v = src[k]; ss += v*v; }
    red[threadIdx.x] = ss; __syncthreads();
    for (int s = blockDim.x>>1; s>0; s>>=1) {
        if (threadIdx.x < s) red[threadIdx.x] += red[threadIdx.x+s];
        __syncthreads();
    }
    float sc = fminf(1.f, 10.f/(sqrtf(red[0])+1e-7f));
    for (int k = threadIdx.x; k < EE; k += blockDim.x) {
        float v = src[k]*sc;
        __nv_bfloat16 h = __float2bfloat16(v);
        g_x_hi[(size_t)row*EEP + k] = h;
        g_x_lo[(size_t)row*EEP + k] = __float2bfloat16(v - __bfloat162float(h));
    }
    for (int k = EE + threadIdx.x; k < EEP; k += blockDim.x) {
        g_x_hi[(size_t)row*EEP + k] = __float2bfloat16(0.f);
        g_x_lo[(size_t)row*EEP + k] = __float2bfloat16(0.f);
    }
}

// plain GEMM for gi one-shot (NT=3)
__global__ __launch_bounds__(512) void mma_gemm(
    const __nv_bfloat16* __restrict__ Ahi, const __nv_bfloat16* __restrict__ Alo, int lda,
    const __nv_bfloat16* __restrict__ Bhi, const __nv_bfloat16* __restrict__ Blo, int ldb,
    int K, float* __restrict__ Cf, int N)
{
    extern __shared__ char sm[];
    mma_body<EPI_C,3>(sm, blockIdx.x, blockIdx.y, Ahi, Alo, lda, Bhi, Blo, ldb,
                      K, Cf, N, nullptr, nullptr, nullptr, nullptr,
                      nullptr, 0, 0, nullptr, nullptr, nullptr, nullptr, nullptr, nullptr, 0,
                      nullptr, nullptr, nullptr);
}

// ---------------- launch ------------------------------------------------------
extern "C" void kernel_launch(void* const* d_in, const int* in_sizes, int n_in,
                              void* d_out, int out_size)
{
    const int*   tokens  = (const int*)  d_in[0];
    const float* w2v     = (const float*)d_in[1];
    const float* enc_Wih = (const float*)d_in[2];
    const float* enc_Whh = (const float*)d_in[3];
    const float* enc_bih = (const float*)d_in[4];
    const float* enc_bhh = (const float*)d_in[5];
    const float* dec_emb = (const float*)d_in[6];
    const float* attn_W  = (const float*)d_in[7];
    const float* attn_b  = (const float*)d_in[8];
    const float* comb_W  = (const float*)d_in[9];
    const float* comb_b  = (const float*)d_in[10];
    const float* dec_Wih = (const float*)d_in[11];
    const float* dec_Whh = (const float*)d_in[12];
    const float* dec_bih = (const float*)d_in[13];
    const float* dec_bhh = (const float*)d_in[14];
    const float* out_W   = (const float*)d_in[15];
    const float* out_b   = (const float*)d_in[16];
    const float* bn1     = (const float*)d_in[17];
    const float* bn2     = (const float*)d_in[18];
    float* out = (float*)d_out;

    __nv_bfloat16 *pxh, *pxl, *pw_eih_h, *pw_eih_l;
    float *pgi_all;
    cudaGetSymbolAddress((void**)&pxh, g_x_hi);
    cudaGetSymbolAddress((void**)&pxl, g_x_lo);
    cudaGetSymbolAddress((void**)&pw_eih_h, g_wencih_hi);
    cudaGetSymbolAddress((void**)&pw_eih_l, g_wencih_lo);
    cudaGetSymbolAddress((void**)&pgi_all,  g_gi_all);

    const int STG3 = 32768 + 2*96*128;     // 57344
    const int STG4 = 32768 + 2*128*128;    // 65536
    const int SMEM_G   = 2 * STG3;         // 114688
    const int SMEM_DEC = 2 * STG4;         // 131072
    cudaFuncSetAttribute(mma_gemm,       cudaFuncAttributeMaxDynamicSharedMemorySize, SMEM_G);
    cudaFuncSetAttribute(enc_persistent, cudaFuncAttributeMaxDynamicSharedMemorySize, SMEM_G);
    cudaFuncSetAttribute(dec_persistent, cudaFuncAttributeMaxDynamicSharedMemorySize, SMEM_DEC);

    init_kernel<<<2048, 256>>>();                                          // 0
    split_a_kernel<<<(3*HH*EEP + 3*HH*HH + 255)/256, 256>>>(enc_Wih, enc_Whh);    // 1
    split_b_kernel<<<(2*3*HH*HH + HH*CATW + TT*HH + 255)/256, 256>>>(      // 2
        dec_Wih, dec_Whh, comb_W, out_W);
    embed_renorm_kernel<<<BL, 128>>>(tokens, w2v);                         // 3
    mma_gemm<<<dim3(3*HH/96, BL/128), 512, SMEM_G>>>(                      // 4
        pxh, pxl, EEP, pw_eih_h, pw_eih_l, EEP, EEP, pgi_all, 3*HH);
    enc_persistent<<<128, 512, SMEM_G>>>(enc_bih, enc_bhh);                // 5
    dec_persistent<<<128, 512, SMEM_DEC>>>(dec_emb, attn_W, attn_b,        // 6
        out_b, bn1, comb_b, bn2, dec_bih, dec_bhh, out);
}

// round 17
// speedup vs baseline: 1.1310x; 1.0285x over previous
#include <cuda_runtime.h>
#include <cuda_bf16.h>
#include <math.h>
#include <stdint.h>

#define BB 512
#define LL 25
#define EE 300
#define EEP 320
#define HH 1024
#define DD 256
#define TT 128
#define BL (BB*LL)
#define CATW (DD+HH)

// ---------------- scratch ----------------------------------------------------
__device__ __nv_bfloat16 g_x_hi[BL*EEP], g_x_lo[BL*EEP];
__device__ float g_gi_all[BL*3*HH];          // PERMUTED cols n=3j+gate
__device__ float g_enc_out[BL*HH];
__device__ float g_h[BB*HH];
__device__ __nv_bfloat16 g_h_hi[BB*HH],  g_h_lo[BB*HH];
__device__ __nv_bfloat16 g_h_hi2[BB*HH], g_h_lo2[BB*HH];
__device__ __nv_bfloat16 g_hb_hi[BB*HH], g_hb_lo[BB*HH];   // bn1(h) split
__device__ float g_gh[BB*3*HH];              // PERMUTED cols
__device__ float g_logits[2*BB*TT];          // split-K partials
__device__ __nv_bfloat16 g_cat_hi[BB*CATW], g_cat_lo[BB*CATW];
__device__ __nv_bfloat16 g_o_hi[BB*HH], g_o_lo[BB*HH];
__device__ __nv_bfloat16 g_wencih_hi[3*HH*EEP], g_wencih_lo[3*HH*EEP];
__device__ __nv_bfloat16 g_wenchh_hi[3*HH*HH],  g_wenchh_lo[3*HH*HH];
__device__ __nv_bfloat16 g_wdecih_hi[3*HH*HH],  g_wdecih_lo[3*HH*HH];
__device__ __nv_bfloat16 g_wdechh_hi[3*HH*HH],  g_wdechh_lo[3*HH*HH];
__device__ __nv_bfloat16 g_wcomb_hi[HH*CATW],   g_wcomb_lo[HH*CATW];
__device__ __nv_bfloat16 g_wout_hi[TT*HH],      g_wout_lo[TT*HH];

__device__ unsigned g_bcnt[8];
__device__ volatile unsigned g_bgen[8];

__device__ __forceinline__ float sigmoidf_(float x) { return 1.f/(1.f+expf(-x)); }

__device__ __forceinline__ uint32_t smem_u32(const void* p) {
    uint32_t a;
    asm("{ .reg .u64 t; cvta.to.shared.u64 t, %1; cvt.u32.u64 %0, t; }" : "=r"(a) : "l"(p));
    return a;
}

__device__ __forceinline__ void gbar(int id, unsigned &gen, unsigned nb)
{
    __syncthreads();
    if (threadIdx.x == 0) {
        __threadfence();
        unsigned my = gen;
        if (atomicAdd(&g_bcnt[id], 1u) == nb - 1u) {
            g_bcnt[id] = 0;
            __threadfence();
            g_bgen[id] = my + 1u;
        } else {
            while (g_bgen[id] == my) { }
        }
        __threadfence();
    }
    __syncthreads();
    gen += 1u;
}

#define LDM4(r, addr) \
    asm volatile("ldmatrix.sync.aligned.m8n8.x4.shared.b16 {%0,%1,%2,%3}, [%4];" \
        : "=r"((r)[0]), "=r"((r)[1]), "=r"((r)[2]), "=r"((r)[3]) : "r"(addr))
#define LDM2(r, addr) \
    asm volatile("ldmatrix.sync.aligned.m8n8.x2.shared.b16 {%0,%1}, [%2];" \
        : "=r"((r)[0]), "=r"((r)[1]) : "r"(addr))
#define MMA16816(d, a, b) \
    asm volatile("mma.sync.aligned.m16n8k16.row.col.f32.bf16.bf16.f32 " \
        "{%0,%1,%2,%3}, {%4,%5,%6,%7}, {%8,%9}, {%0,%1,%2,%3};" \
        : "+f"((d)[0]), "+f"((d)[1]), "+f"((d)[2]), "+f"((d)[3]) \
        : "r"((a)[0]), "r"((a)[1]), "r"((a)[2]), "r"((a)[3]), "r"((b)[0]), "r"((b)[1]))
#define CPASYNC16(dst, src) \
    asm volatile("cp.async.cg.shared.global [%0], [%1], 16;" :: "r"(dst), "l"(src))

enum { EPI_C=0, EPI_COMB=1, EPI_GRU=2 };
#define GHS_LD 100

// 3-stage cp.async pipeline; T4: add al*bl term (logits only)
template<int EPI, int NT, int T4 = 0>
__device__ __forceinline__ void mma_body(
    char* sm, int bx, int by,
    const __nv_bfloat16* __restrict__ Ahi, const __nv_bfloat16* __restrict__ Alo, int lda,
    const __nv_bfloat16* __restrict__ Bhi, const __nv_bfloat16* __restrict__ Blo, int ldb,
    int K, float* __restrict__ Cf, int N,
    const float* __restrict__ bias, const float* __restrict__ bn,
    __nv_bfloat16* __restrict__ Ohi, __nv_bfloat16* __restrict__ Olo,
    const float* __restrict__ Gmat, int gstride, int l_is_gh,
    const float* __restrict__ bih, const float* __restrict__ bhh,
    float* __restrict__ hstate,
    __nv_bfloat16* __restrict__ hhi_out, __nv_bfloat16* __restrict__ hlo_out,
    float* __restrict__ eout, int eout_stride,
    const float* __restrict__ bnh,
    __nv_bfloat16* __restrict__ hbhi, __nv_bfloat16* __restrict__ hblo)
{
    constexpr int WNT = NT * 8;
    constexpr int NR  = 4 * WNT;
    constexpr int BLO = NR * 128;
    constexpr int STG = 32768 + 2 * NR * 128;

    const int tid  = threadIdx.x;
    const int lane = tid & 31, wid = tid >> 5;
    const int wm   = wid & 3;
    const int wn   = wid >> 2;
    const int m0   = by * 128, n0 = bx * NR;
    const uint32_t sbase = smem_u32(sm);

    const int sr = tid >> 2, sq = tid & 3;
    const __nv_bfloat16* pa_hi = Ahi + (size_t)(m0 + sr) * lda;
    const __nv_bfloat16* pa_lo = Alo + (size_t)(m0 + sr) * lda;
    const int rbq = (sr < NR) ? sr : (NR - 1);
    const __nv_bfloat16* pb_hi = Bhi + (size_t)(n0 + rbq) * ldb;
    const __nv_bfloat16* pb_lo = Blo + (size_t)(n0 + rbq) * ldb;
    const uint32_t swr = (uint32_t)(sr & 7);

    auto stage = [&](int buf, int k0) {
        uint32_t dbase = sbase + (uint32_t)buf * STG;
        uint32_t da = dbase + (uint32_t)sr * 128u;
        #pragma unroll
        for (int c = 0; c < 2; c++) {
            uint32_t g = (uint32_t)(sq * 2 + c);
            uint32_t off = ((g ^ swr) << 4);
            CPASYNC16(da + off,          pa_hi + k0 + g * 8);
            CPASYNC16(da + 16384u + off, pa_lo + k0 + g * 8);
        }
        if (sr < NR) {
            uint32_t db = dbase + 32768u + (uint32_t)sr * 128u;
            #pragma unroll
            for (int c = 0; c < 2; c++) {
                uint32_t g = (uint32_t)(sq * 2 + c);
                uint32_t off = ((g ^ swr) << 4);
                CPASYNC16(db + off,                 pb_hi + k0 + g * 8);
                CPASYNC16(db + (uint32_t)BLO + off, pb_lo + k0 + g * 8);
            }
        }
        asm volatile("cp.async.commit_group;" ::: "memory");
    };

    float acc[2][NT][4];
    #pragma unroll
    for (int i = 0; i < 2; i++)
        #pragma unroll
        for (int j = 0; j < NT; j++)
            #pragma unroll
            for (int q = 0; q < 4; q++) acc[i][j][q] = 0.f;

    const int nt = K / 64;
    stage(0, 0);
    if (nt > 1) stage(1, 64);
    int buf = 0;
    for (int it = 0; it < nt; it++) {
        if (it + 1 < nt) {
            asm volatile("cp.async.wait_group 1;" ::: "memory");
        } else {
            asm volatile("cp.async.wait_group 0;" ::: "memory");
        }
        __syncthreads();
        if (it + 2 < nt) {
            int nb = buf + 2; if (nb >= 3) nb -= 3;
            stage(nb, (it + 2) * 64);
        }

        uint32_t tb = sbase + (uint32_t)buf * STG;
        #pragma unroll
        for (int ks = 0; ks < 4; ks++) {
            const int g0 = ks * 2;
            uint32_t ah[2][4], al[2][4];
            {
                int row_off = ((lane >> 3) & 1) * 8 + (lane & 7);
                int g = g0 + (lane >> 4);
                #pragma unroll
                for (int mt = 0; mt < 2; mt++) {
                    int row = wm * 32 + mt * 16 + row_off;
                    uint32_t addr = tb + (uint32_t)row * 128u
                                  + (uint32_t)((g ^ (row & 7)) << 4);
                    LDM4(ah[mt], addr);
                    LDM4(al[mt], addr + 16384u);
                }
            }
            uint32_t bh[NT][2], bl[NT][2];
            {
                int grp = lane >> 3;
                #pragma unroll
                for (int p = 0; p < NT/2; p++) {
                    int tile = 2 * p + (grp >> 1);
                    int g = g0 + (grp & 1);
                    int nrow = wn * WNT + tile * 8 + (lane & 7);
                    uint32_t addr = tb + 32768u + (uint32_t)nrow * 128u
                                  + (uint32_t)((g ^ (nrow & 7)) << 4);
                    uint32_t r4[4];
                    LDM4(r4, addr);
                    bh[2*p][0] = r4[0]; bh[2*p][1] = r4[1];
                    bh[2*p+1][0] = r4[2]; bh[2*p+1][1] = r4[3];
                    LDM4(r4, addr + BLO);
                    bl[2*p][0] = r4[0]; bl[2*p][1] = r4[1];
                    bl[2*p+1][0] = r4[2]; bl[2*p+1][1] = r4[3];
                }
                if (NT & 1) {
                    int tile = NT - 1;
                    int g = g0 + (grp & 1);
                    int nrow = wn * WNT + tile * 8 + (lane & 7);
                    uint32_t addr = tb + 32768u + (uint32_t)nrow * 128u
                                  + (uint32_t)((g ^ (nrow & 7)) << 4);
                    LDM2(bh[NT-1], addr);
                    LDM2(bl[NT-1], addr + BLO);
                }
            }
            #pragma unroll
            for (int mt = 0; mt < 2; mt++)
                #pragma unroll
                for (int ntl = 0; ntl < NT; ntl++)
                    MMA16816(acc[mt][ntl], ah[mt], bh[ntl]);
            #pragma unroll
            for (int mt = 0; mt < 2; mt++)
                #pragma unroll
                for (int ntl = 0; ntl < NT; ntl++)
                    MMA16816(acc[mt][ntl], ah[mt], bl[ntl]);
            #pragma unroll
            for (int mt = 0; mt < 2; mt++)
                #pragma unroll
                for (int ntl = 0; ntl < NT; ntl++)
                    MMA16816(acc[mt][ntl], al[mt], bh[ntl]);
            if (T4) {
                #pragma unroll
                for (int mt = 0; mt < 2; mt++)
                    #pragma unroll
                    for (int ntl = 0; ntl < NT; ntl++)
                        MMA16816(acc[mt][ntl], al[mt], bl[ntl]);
            }
        }
        if (++buf >= 3) buf = 0;
    }

    if (EPI == EPI_GRU) {
        __syncthreads();   // all threads out of the MMA loop before smem reuse
        float* ghs = (float*)sm;
        #pragma unroll
        for (int mt = 0; mt < 2; mt++) {
            #pragma unroll
            for (int ntl = 0; ntl < NT; ntl++) {
                int rl = wm*32 + mt*16 + (lane >> 2);
                int cl = wn*WNT + ntl*8 + (lane & 3)*2;
                ghs[rl*GHS_LD + cl]     = acc[mt][ntl][0];
                ghs[rl*GHS_LD + cl + 1] = acc[mt][ntl][1];
                ghs[(rl+8)*GHS_LD + cl]     = acc[mt][ntl][2];
                ghs[(rl+8)*GHS_LD + cl + 1] = acc[mt][ntl][3];
            }
        }
        __syncthreads();
        float s1=0.f, mu1=0.f, be1=0.f;
        if (hbhi) { s1 = bnh[0]*rsqrtf(bnh[3]+1e-5f); mu1 = bnh[2]; be1 = bnh[1]; }
        const int j0 = n0 / 3;
        for (int i = tid; i < 128*32; i += 512) {
            int bl = i >> 5, jl = i & 31;
            int b = m0 + bl;
            int j = j0 + jl;
            float L0 = ghs[bl*GHS_LD + 3*jl + 0];
            float L1 = ghs[bl*GHS_LD + 3*jl + 1];
            float L2 = ghs[bl*GHS_LD + 3*jl + 2];
            const float* G = Gmat + (size_t)b*gstride + (n0 + 3*jl);
            float G0 = G[0], G1 = G[1], G2 = G[2];
            float i_r, i_z, i_n, h_r, h_z, h_n;
            if (l_is_gh) { h_r=L0; h_z=L1; h_n=L2; i_r=G0; i_z=G1; i_n=G2; }
            else         { i_r=L0; i_z=L1; i_n=L2; h_r=G0; h_z=G1; h_n=G2; }
            i_r += bih[j]; i_z += bih[HH+j]; i_n += bih[2*HH+j];
            h_r += bhh[j]; h_z += bhh[HH+j]; h_n += bhh[2*HH+j];
            float r = sigmoidf_(i_r + h_r);
            float z = sigmoidf_(i_z + h_z);
            float n = tanhf(i_n + r*h_n);
            float hold = hstate[(size_t)b*HH + j];
            float hn2 = (1.f - z)*n + z*hold;
            hstate[(size_t)b*HH + j] = hn2;
            __nv_bfloat16 hb = __float2bfloat16(hn2);
            hhi_out[(size_t)b*HH + j] = hb;
            hlo_out[(size_t)b*HH + j] = __float2bfloat16(hn2 - __bfloat162float(hb));
            if (hbhi) {
                float hv = (hn2 - mu1)*s1 + be1;
                __nv_bfloat16 hbb = __float2bfloat16(hv);
                hbhi[(size_t)b*HH + j] = hbb;
                hblo[(size_t)b*HH + j] = __float2bfloat16(hv - __bfloat162float(hbb));
            }
            if (eout) eout[(size_t)b*eout_stride + j] = hn2;
        }
        return;
    }

    float s = 1.f, mu = 0.f, be = 0.f;
    if (EPI == EPI_COMB) { s = bn[0]*rsqrtf(bn[3]+1e-5f); mu = bn[2]; be = bn[1]; }
    #pragma unroll
    for (int mt = 0; mt < 2; mt++) {
        #pragma unroll
        for (int ntl = 0; ntl < NT; ntl++) {
            int row = m0 + wm*32 + mt*16 + (lane >> 2);
            int col = n0 + wn*WNT + ntl*8 + (lane & 3)*2;
            if (EPI == EPI_C) {
                *(float2*)(Cf + (size_t)row*N + col) =
                    make_float2(acc[mt][ntl][0], acc[mt][ntl][1]);
                *(float2*)(Cf + (size_t)(row+8)*N + col) =
                    make_float2(acc[mt][ntl][2], acc[mt][ntl][3]);
            } else {
                #pragma unroll
                for (int q = 0; q < 4; q++) {
                    int r = row + (q >> 1)*8;
                    int c = col + (q & 1);
                    float v = acc[mt][ntl][q] + bias[c];
                    v = fmaxf((v - mu)*s + be, 0.f);
                    __nv_bfloat16 hv = __float2bfloat16(v);
                    Ohi[(size_t)r*HH + c] = hv;
                    Olo[(size_t)r*HH + c] = __float2bfloat16(v - __bfloat162float(hv));
                }
            }
        }
    }
}

// ---------------- lsm+attn phase (two 256-thread named-barrier groups) -------
struct LAS {
    float sh[HH];
    float red[256];
    int   redi[128];
    float semb[DD];
    float saw[32];
    float pad[8];
};
#define NBAR(g) asm volatile("bar.sync %0, 256;" :: "r"((g)+1) : "memory")

__device__ void lsm_attn_phase(char* smb, int blk,
    const float* __restrict__ dec_emb,
    const float* __restrict__ attn_W, const float* __restrict__ attn_b,
    const float* __restrict__ ob, float* __restrict__ out,
    int lsm_t, int do_attn)
{
    const int tid = threadIdx.x;
    const int group = tid >> 8;
    const int gtid = tid & 255;
    LAS* S = ((LAS*)smb) + group;
    __syncthreads();

    for (int rep = 0; rep < 2; rep++) {
        int b = blk + (group*2 + rep)*128;
        for (int k = gtid; k < HH; k += 256) S->sh[k] = g_h[(size_t)b*HH + k];
        NBAR(group);

        int token;
        if (lsm_t >= 0) {
            float x = 0.f;
            if (gtid < 128)
                x = g_logits[(size_t)b*TT + gtid]
                  + g_logits[(size_t)BB*TT + (size_t)b*TT + gtid] + ob[gtid];
            if (gtid < 128) { S->red[gtid] = x; S->redi[gtid] = gtid; }
            NBAR(group);
            for (int st = 64; st > 0; st >>= 1) {
                if (gtid < st && S->red[gtid+st] > S->red[gtid]) {
                    S->red[gtid] = S->red[gtid+st]; S->redi[gtid] = S->redi[gtid+st];
                }
                NBAR(group);
            }
            float m = S->red[0]; int am = S->redi[0];
            NBAR(group);
            S->red[gtid] = (gtid < 128) ? expf(x - m) : 0.f;
            NBAR(group);
            for (int st = 128; st > 0; st >>= 1) {
                if (gtid < st) S->red[gtid] += S->red[gtid+st];
                NBAR(group);
            }
            float lse = logf(S->red[0]);
            if (gtid < 128) out[((size_t)b*LL + lsm_t)*TT + gtid] = x - m - lse;
            token = am;
            NBAR(group);
        } else {
            token = TT;  // SOS
        }

        if (do_attn) {
            float val = dec_emb[(size_t)token*DD + gtid];
            S->red[gtid] = val*val; NBAR(group);
            for (int st=128; st>0; st>>=1) { if (gtid<st) S->red[gtid]+=S->red[gtid+st]; NBAR(group); }
            float sc = fminf(1.f, 1.f/(sqrtf(S->red[0])+1e-7f));
            float e = val*sc;
            S->semb[gtid] = e;
            {
                __nv_bfloat16 h = __float2bfloat16(e);
                g_cat_hi[(size_t)b*CATW + gtid] = h;
                g_cat_lo[(size_t)b*CATW + gtid] = __float2bfloat16(e - __bfloat162float(h));
            }
            NBAR(group);

            int warp = gtid>>5, lane = gtid&31;
            for (int l = warp; l < LL; l += 8) {
                const float* w = attn_W + (size_t)l*CATW;
                float acc = 0.f;
                for (int k = lane; k < DD; k += 32) acc += S->semb[k]*w[k];
                for (int k = lane; k < HH; k += 32) acc += S->sh[k]*w[DD+k];
                for (int o=16;o;o>>=1) acc += __shfl_xor_sync(0xffffffffu, acc, o);
                if (lane==0) S->saw[l] = acc + attn_b[l];
            }
            NBAR(group);
            if (warp==0) {
                float v = (lane<LL)? S->saw[lane] : -1e30f;
                float m = v;
                for (int o=16;o;o>>=1) m = fmaxf(m, __shfl_xor_sync(0xffffffffu, m, o));
                float ex = (lane<LL)? expf(v-m) : 0.f;
                float sm2 = ex;
                for (int o=16;o;o>>=1) sm2 += __shfl_xor_sync(0xffffffffu, sm2, o);
                if (lane<LL) S->saw[lane] = ex/sm2;
            }
            NBAR(group);

            const float* eo = g_enc_out + (size_t)b*LL*HH;
            for (int j = gtid; j < HH; j += 256) {
                float acc = 0.f;
                #pragma unroll
                for (int l=0;l<LL;l++) acc += S->saw[l]*eo[(size_t)l*HH + j];
                __nv_bfloat16 h = __float2bfloat16(acc);
                g_cat_hi[(size_t)b*CATW + DD + j] = h;
                g_cat_lo[(size_t)b*CATW + DD + j] = __float2bfloat16(acc - __bfloat162float(h));
            }
            NBAR(group);
        }
    }
    __syncthreads();
}

// ---------------- persistent encoder -----------------------------------------
__global__ __launch_bounds__(512) void enc_persistent(
    const float* __restrict__ bih, const float* __restrict__ bhh)
{
    extern __shared__ char sm[];
    unsigned gen = 0;
    const int bx = blockIdx.x & 31, by = blockIdx.x >> 5;
    for (int t = 0; t < LL; t++) {
        int p = t & 1;
        const __nv_bfloat16* ah = p ? g_h_hi2 : g_h_hi;
        const __nv_bfloat16* al = p ? g_h_lo2 : g_h_lo;
        __nv_bfloat16* oh = p ? g_h_hi : g_h_hi2;
        __nv_bfloat16* ol = p ? g_h_lo : g_h_lo2;
        mma_body<EPI_GRU,3>(sm, bx, by, ah, al, HH,
                            g_wenchh_hi, g_wenchh_lo, HH, HH,
                            nullptr, 3*HH, nullptr, nullptr, nullptr, nullptr,
                            g_gi_all + (size_t)t*3*HH, LL*3*HH, 1,
                            bih, bhh, g_h, oh, ol,
                            g_enc_out + (size_t)t*HH, LL*HH,
                            nullptr, nullptr, nullptr);
        if (t < LL-1) gbar(by, gen, 32);
    }
}

// ---------------- persistent decoder -----------------------------------------
__global__ __launch_bounds__(512) void dec_persistent(
    const float* __restrict__ dec_emb,
    const float* __restrict__ attn_W, const float* __restrict__ attn_b,
    const float* __restrict__ out_b, const float* __restrict__ bn1,
    const float* __restrict__ comb_b, const float* __restrict__ bn2,
    const float* __restrict__ dec_bih, const float* __restrict__ dec_bhh,
    float* __restrict__ out)
{
    extern __shared__ char sm[];
    unsigned gen = 0;
    const int bi = blockIdx.x;

    lsm_attn_phase(sm, bi, dec_emb, attn_W, attn_b, out_b, out, -1, 1);
    gbar(4, gen, gridDim.x);
    if (bi < 96) {
        mma_body<EPI_C,4>(sm, bi % 24, bi / 24,
            g_h_hi2, g_h_lo2, HH, g_wdechh_hi, g_wdechh_lo, HH, HH,
            g_gh, 3*HH, nullptr, nullptr, nullptr, nullptr,
            nullptr, 0, 0, nullptr, nullptr, nullptr, nullptr, nullptr, nullptr, 0,
            nullptr, nullptr, nullptr);
    }
    gbar(4, gen, gridDim.x);

    for (int t = 0; t < LL; t++) {
        // P1: comb (cat -> o), NT=1, 128 blocks
        mma_body<EPI_COMB,1>(sm, bi & 31, bi >> 5,
            g_cat_hi, g_cat_lo, CATW, g_wcomb_hi, g_wcomb_lo, CATW, CATW,
            nullptr, HH, comb_b, bn2, g_o_hi, g_o_lo,
            nullptr, 0, 0, nullptr, nullptr, nullptr, nullptr, nullptr, nullptr, 0,
            nullptr, nullptr, nullptr);
        gbar(4, gen, gridDim.x);
        // P2: gi + GRU (writes bn1(h) split)
        mma_body<EPI_GRU,3>(sm, bi & 31, bi >> 5,
            g_o_hi, g_o_lo, HH, g_wdecih_hi, g_wdecih_lo, HH, HH,
            nullptr, 3*HH, nullptr, nullptr, nullptr, nullptr,
            g_gh, 3*HH, 0, dec_bih, dec_bhh, g_h, g_h_hi2, g_h_lo2,
            nullptr, 0,
            bn1, g_hb_hi, g_hb_lo);
        gbar(4, gen, gridDim.x);
        // P3: gh(t+1) on 0..95 (skip last); logits 4-term split-K on 96..103
        if (bi < 96) {
            if (t < LL-1) {
                mma_body<EPI_C,4>(sm, bi % 24, bi / 24,
                    g_h_hi2, g_h_lo2, HH, g_wdechh_hi, g_wdechh_lo, HH, HH,
                    g_gh, 3*HH, nullptr, nullptr, nullptr, nullptr,
                    nullptr, 0, 0, nullptr, nullptr, nullptr, nullptr, nullptr, nullptr, 0,
                    nullptr, nullptr, nullptr);
            }
        } else if (bi < 104) {
            int li = bi - 96;
            int half = li >> 2;
            int byy  = li & 3;
            mma_body<EPI_C,4,1>(sm, 0, byy,
                g_hb_hi + half*512, g_hb_lo + half*512, HH,
                g_wout_hi + half*512, g_wout_lo + half*512, HH, 512,
                g_logits + (size_t)half*BB*TT, TT, nullptr, nullptr, nullptr, nullptr,
                nullptr, 0, 0, nullptr, nullptr, nullptr, nullptr, nullptr, nullptr, 0,
                nullptr, nullptr, nullptr);
        }
        gbar(4, gen, gridDim.x);
        // P4: lsm(t) + argmax + attn(t+1)
        lsm_attn_phase(sm, bi, dec_emb, attn_W, attn_b, out_b, out,
                       t, (t < LL-1));
        if (t < LL-1) gbar(4, gen, gridDim.x);
    }
}

// ---------------- fused setup kernel -------------------------------------------
__device__ __forceinline__ void split_perm(const float* src, __nv_bfloat16* hi,
                                           __nv_bfloat16* lo, int idx, int K, int Kpad)
{
    int n_new = idx / Kpad, k = idx - n_new*Kpad;
    int j = n_new / 3, gate = n_new - 3*j;
    float v = (k < K) ? src[(size_t)(gate*HH + j)*K + k] : 0.f;
    __nv_bfloat16 h = __float2bfloat16(v);
    hi[idx] = h;
    lo[idx] = __float2bfloat16(v - __bfloat162float(h));
}
__device__ __forceinline__ void split_seg(const float* src, __nv_bfloat16* hi,
                                          __nv_bfloat16* lo, int idx, int K, int Kpad)
{
    int r = idx / Kpad, k = idx - r*Kpad;
    float v = (k < K) ? src[(size_t)r*K + k] : 0.f;
    __nv_bfloat16 h = __float2bfloat16(v);
    hi[idx] = h;
    lo[idx] = __float2bfloat16(v - __bfloat162float(h));
}

#define NB_INIT  2048
#define NB_SPA   16128   // (3*HH*EEP + 3*HH*HH)/256
#define NB_SPB   30208   // (2*3*HH*HH + HH*CATW + TT*HH)/256
#define NB_EMB   BL

__global__ __launch_bounds__(256) void setup_kernel(
    const int* __restrict__ tokens, const float* __restrict__ w2v,
    const float* __restrict__ w_eih, const float* __restrict__ w_ehh,
    const float* __restrict__ w_dih, const float* __restrict__ w_dhh,
    const float* __restrict__ w_cmb, const float* __restrict__ w_out)
{
    int blk = blockIdx.x;
    if (blk < NB_INIT) {
        int idx = blk*256 + threadIdx.x;
        if (idx < BB*HH) {
            g_h[idx] = 0.f;
            g_h_hi[idx] = __float2bfloat16(0.f);
            g_h_lo[idx] = __float2bfloat16(0.f);
        }
        if (idx < 8) { g_bcnt[idx] = 0; g_bgen[idx] = 0; }
        return;
    }
    blk -= NB_INIT;
    if (blk < NB_SPA) {
        int idx = blk*256 + threadIdx.x;
        const int n0 = 3*HH*EEP, n1 = 3*HH*HH;
        if (idx < n0) split_perm(w_eih, g_wencih_hi, g_wencih_lo, idx, EE, EEP);
        else if (idx < n0 + n1) split_perm(w_ehh, g_wenchh_hi, g_wenchh_lo, idx - n0, HH, HH);
        return;
    }
    blk -= NB_SPA;
    if (blk < NB_SPB) {
        int idx = blk*256 + threadIdx.x;
        const int n0 = 3*HH*HH, n1 = 3*HH*HH, n2 = HH*CATW, n3 = TT*HH;
        if (idx < n0) split_perm(w_dih, g_wdecih_hi, g_wdecih_lo, idx, HH, HH);
        else if (idx < n0+n1) split_perm(w_dhh, g_wdechh_hi, g_wdechh_lo, idx - n0, HH, HH);
        else if (idx < n0+n1+n2) split_seg(w_cmb, g_wcomb_hi, g_wcomb_lo, idx - n0 - n1, CATW, CATW);
        else if (idx < n0+n1+n2+n3) split_seg(w_out, g_wout_hi, g_wout_lo, idx - n0 - n1 - n2, HH, HH);
        return;
    }
    blk -= NB_SPB;
    // embedding + renorm (256 threads)
    {
        int row = blk;
        int tok = tokens[row];
        const float* src = w2v + (size_t)tok*EE;
        __shared__ float red[256];
        float ss = 0.f;
        for (int k = threadIdx.x; k < EE; k += 256) { float v = src[k]; ss += v*v; }
        red[threadIdx.x] = ss; __syncthreads();
        for (int s = 128; s > 0; s >>= 1) {
            if (threadIdx.x < s) red[threadIdx.x] += red[threadIdx.x+s];
            __syncthreads();
        }
        float sc = fminf(1.f, 10.f/(sqrtf(red[0])+1e-7f));
        for (int k = threadIdx.x; k < EE; k += 256) {
            float v = src[k]*sc;
            __nv_bfloat16 h = __float2bfloat16(v);
            g_x_hi[(size_t)row*EEP + k] = h;
            g_x_lo[(size_t)row*EEP + k] = __float2bfloat16(v - __bfloat162float(h));
        }
        for (int k = EE + threadIdx.x; k < EEP; k += 256) {
            g_x_hi[(size_t)row*EEP + k] = __float2bfloat16(0.f);
            g_x_lo[(size_t)row*EEP + k] = __float2bfloat16(0.f);
        }
    }
}

// plain GEMM for gi one-shot (NT=3)
__global__ __launch_bounds__(512) void mma_gemm(
    const __nv_bfloat16* __restrict__ Ahi, const __nv_bfloat16* __restrict__ Alo, int lda,
    const __nv_bfloat16* __restrict__ Bhi, const __nv_bfloat16* __restrict__ Blo, int ldb,
    int K, float* __restrict__ Cf, int N)
{
    extern __shared__ char sm[];
    mma_body<EPI_C,3>(sm, blockIdx.x, blockIdx.y, Ahi, Alo, lda, Bhi, Blo, ldb,
                      K, Cf, N, nullptr, nullptr, nullptr, nullptr,
                      nullptr, 0, 0, nullptr, nullptr, nullptr, nullptr, nullptr, nullptr, 0,
                      nullptr, nullptr, nullptr);
}

// ---------------- launch ------------------------------------------------------
extern "C" void kernel_launch(void* const* d_in, const int* in_sizes, int n_in,
                              void* d_out, int out_size)
{
    const int*   tokens  = (const int*)  d_in[0];
    const float* w2v     = (const float*)d_in[1];
    const float* enc_Wih = (const float*)d_in[2];
    const float* enc_Whh = (const float*)d_in[3];
    const float* enc_bih = (const float*)d_in[4];
    const float* enc_bhh = (const float*)d_in[5];
    const float* dec_emb = (const float*)d_in[6];
    const float* attn_W  = (const float*)d_in[7];
    const float* attn_b  = (const float*)d_in[8];
    const float* comb_W  = (const float*)d_in[9];
    const float* comb_b  = (const float*)d_in[10];
    const float* dec_Wih = (const float*)d_in[11];
    const float* dec_Whh = (const float*)d_in[12];
    const float* dec_bih = (const float*)d_in[13];
    const float* dec_bhh = (const float*)d_in[14];
    const float* out_W   = (const float*)d_in[15];
    const float* out_b   = (const float*)d_in[16];
    const float* bn1     = (const float*)d_in[17];
    const float* bn2     = (const float*)d_in[18];
    float* out = (float*)d_out;

    __nv_bfloat16 *pxh, *pxl, *pw_eih_h, *pw_eih_l;
    float *pgi_all;
    cudaGetSymbolAddress((void**)&pxh, g_x_hi);
    cudaGetSymbolAddress((void**)&pxl, g_x_lo);
    cudaGetSymbolAddress((void**)&pw_eih_h, g_wencih_hi);
    cudaGetSymbolAddress((void**)&pw_eih_l, g_wencih_lo);
    cudaGetSymbolAddress((void**)&pgi_all,  g_gi_all);

    const int STG3 = 32768 + 2*96*128;     // 57344
    const int STG4 = 32768 + 2*128*128;    // 65536
    const int SMEM_G   = 3 * STG3;         // 172032 (3-stage)
    const int SMEM_DEC = 3 * STG4;         // 196608 (3-stage)
    cudaFuncSetAttribute(mma_gemm,       cudaFuncAttributeMaxDynamicSharedMemorySize, SMEM_G);
    cudaFuncSetAttribute(enc_persistent, cudaFuncAttributeMaxDynamicSharedMemorySize, SMEM_G);
    cudaFuncSetAttribute(dec_persistent, cudaFuncAttributeMaxDynamicSharedMemorySize, SMEM_DEC);

    // 4 launches; dec_persistent is my-index 3 => ncu profiled slot
    setup_kernel<<<NB_INIT + NB_SPA + NB_SPB + NB_EMB, 256>>>(             // 0
        tokens, w2v, enc_Wih, enc_Whh, dec_Wih, dec_Whh, comb_W, out_W);
    mma_gemm<<<dim3(3*HH/96, BL/128), 512, SMEM_G>>>(                      // 1
        pxh, pxl, EEP, pw_eih_h, pw_eih_l, EEP, EEP, pgi_all, 3*HH);
    enc_persistent<<<128, 512, SMEM_G>>>(enc_bih, enc_bhh);                // 2
    dec_persistent<<<128, 512, SMEM_DEC>>>(dec_emb, attn_W, attn_b,        // 3 (profiled)
        out_b, bn1, comb_b, bn2, dec_bih, dec_bhh, out);
}